// round 1
// baseline (speedup 1.0000x reference)
#include <cuda_runtime.h>
#include <math.h>

// ---------------- constants ----------------
#define RMAX 8192
static constexpr float SDF_T = 5e-05f;
static constexpr int   TRACE_G = 8;    // rays per trace block
static constexpr int   TRACE_P = 16;   // points per eval round (2*G)
static constexpr int   SAMP_P  = 20;   // points per sampler round (5 rounds = 100)
static constexpr float INV99   = 1.0f / 99.0f;

// inter-kernel scratch (no allocations allowed)
__device__ float g_smin[RMAX];
__device__ float g_smax[RMAX];
__device__ int   g_mask[RMAX];

// ---------------- batched SDF eval ----------------
// Evaluates sdf(p) for P points. All 256 threads participate.
// pts:  P*3 floats in smem
// h1s:  256*P floats in smem (layout [k][p], k-major, float4-friendly)
// red:  8*P floats in smem
// sdfv: P floats out (smem)
template<int P>
__device__ __forceinline__ void sdf_eval(
    const float* __restrict__ W1, const float* __restrict__ b1,
    const float* __restrict__ W2, const float* __restrict__ b2,
    const float* __restrict__ W3, float b3v,
    const float* pts, float* h1s, float* red, float* sdfv)
{
    const int tid = threadIdx.x;

    // ---- layer 1: h1[k][p] = tanh(p . W1[:,k] + b1[k]) ----
#pragma unroll
    for (int it = 0; it < P; ++it) {
        int idx = it * 256 + tid;       // 0 .. 256*P-1, coalesced writes
        int k = idx / P;
        int p = idx - k * P;
        float x = pts[p * 3 + 0], y = pts[p * 3 + 1], z = pts[p * 3 + 2];
        float v = fmaf(W1[k], x, fmaf(W1[256 + k], y, fmaf(W1[512 + k], z, b1[k])));
        h1s[idx] = tanhf(v);
    }
    __syncthreads();

    // ---- layer 2: thread j owns output neuron j, P accumulators ----
    float acc[P];
#pragma unroll
    for (int p = 0; p < P; ++p) acc[p] = 0.f;
    const int j = tid;
#pragma unroll 2
    for (int k = 0; k < 256; ++k) {
        float w = W2[k * 256 + j];                     // coalesced, L1/L2-resident
        const float4* h4 = reinterpret_cast<const float4*>(h1s + k * P);
#pragma unroll
        for (int q = 0; q < P / 4; ++q) {
            float4 v = h4[q];                          // broadcast LDS.128
            acc[q * 4 + 0] = fmaf(v.x, w, acc[q * 4 + 0]);
            acc[q * 4 + 1] = fmaf(v.y, w, acc[q * 4 + 1]);
            acc[q * 4 + 2] = fmaf(v.z, w, acc[q * 4 + 2]);
            acc[q * 4 + 3] = fmaf(v.w, w, acc[q * 4 + 3]);
        }
    }

    // ---- layer 3: out[p] = base(p) + 0.05*(sum_j tanh(acc+b2[j])*W3[j] + b3) ----
    const float bb2 = b2[j];
    const float w3j = W3[j];
#pragma unroll
    for (int p = 0; p < P; ++p) {
        float m = tanhf(acc[p] + bb2) * w3j;
#pragma unroll
        for (int off = 16; off; off >>= 1)
            m += __shfl_down_sync(0xffffffffu, m, off);
        if ((tid & 31) == 0) red[p * 8 + (tid >> 5)] = m;
    }
    __syncthreads();
    if (tid < P) {
        float s = 0.f;
#pragma unroll
        for (int q = 0; q < 8; ++q) s += red[tid * 8 + q];
        float x = pts[tid * 3 + 0], y = pts[tid * 3 + 1], z = pts[tid * 3 + 2];
        float base = sqrtf(fmaf(x, x, fmaf(y, y, fmaf(z, z, 1e-12f)))) - 0.6f;
        sdfv[tid] = base + 0.05f * (s + b3v);
    }
    __syncthreads();
}

// ---------------- kernel 1: init + sphere tracing ----------------
__global__ __launch_bounds__(256)
void trace_kernel(
    const float* __restrict__ cam_in, const float* __restrict__ ray_in,
    const float* __restrict__ W1, const float* __restrict__ b1,
    const float* __restrict__ W2, const float* __restrict__ b2,
    const float* __restrict__ W3, const float* __restrict__ b3,
    float* __restrict__ out, int R)
{
    __shared__ float h1s[256 * TRACE_P];
    __shared__ float red[8 * TRACE_P];
    __shared__ float pts[TRACE_P * 3];
    __shared__ float sdfv[TRACE_P];
    __shared__ float s_cam[TRACE_G][3], s_ray[TRACE_G][3];
    __shared__ float s_acc_s[TRACE_G], s_acc_e[TRACE_G];
    __shared__ float s_nsdf_s[TRACE_G], s_nsdf_e[TRACE_G];
    __shared__ float s_csdf_s[TRACE_G], s_csdf_e[TRACE_G];
    __shared__ int   s_unfin_s[TRACE_G], s_unfin_e[TRACE_G];
    __shared__ int   s_np_s[TRACE_G], s_np_e[TRACE_G];
    __shared__ int   s_flag;

    const int tid   = threadIdx.x;
    const int rbase = blockIdx.x * TRACE_G;
    const float b3v = b3[0];

    if (tid < TRACE_G) {
        int r = rbase + tid;
        float cx = 0.f, cy = 0.f, cz = 0.f, rx = 0.f, ry = 0.f, rz = 0.f;
        bool valid = (r < R);
        if (valid) {
            cx = cam_in[r * 3 + 0]; cy = cam_in[r * 3 + 1]; cz = cam_in[r * 3 + 2];
            rx = ray_in[r * 3 + 0]; ry = ray_in[r * 3 + 1]; rz = ray_in[r * 3 + 2];
        }
        s_cam[tid][0] = cx; s_cam[tid][1] = cy; s_cam[tid][2] = cz;
        s_ray[tid][0] = rx; s_ray[tid][1] = ry; s_ray[tid][2] = rz;
        float dt = rx * cx + ry * cy + rz * cz;
        float cc = cx * cx + cy * cy + cz * cz;
        float under = dt * dt - (cc - 1.0f);
        bool mi = valid && (under > 0.f);
        float sq = sqrtf(mi ? under : 1.0f);
        float i0 = mi ? fmaxf(-sq - dt, 0.f) : 0.f;
        float i1 = mi ? fmaxf( sq - dt, 0.f) : 0.f;
        s_acc_s[tid] = i0; s_acc_e[tid] = i1;
        s_unfin_s[tid] = mi ? 1 : 0;
        s_unfin_e[tid] = mi ? 1 : 0;
    }
    __syncthreads();

    // round 0: initial sdf at both endpoints
    if (tid < TRACE_P) {
        int g = tid >> 1;
        float a = (tid & 1) ? s_acc_e[g] : s_acc_s[g];
        pts[tid * 3 + 0] = fmaf(a, s_ray[g][0], s_cam[g][0]);
        pts[tid * 3 + 1] = fmaf(a, s_ray[g][1], s_cam[g][1]);
        pts[tid * 3 + 2] = fmaf(a, s_ray[g][2], s_cam[g][2]);
    }
    __syncthreads();
    sdf_eval<TRACE_P>(W1, b1, W2, b2, W3, b3v, pts, h1s, red, sdfv);
    if (tid < TRACE_G) {
        s_nsdf_s[tid] = s_unfin_s[tid] ? sdfv[tid * 2 + 0] : 0.f;
        s_nsdf_e[tid] = s_unfin_e[tid] ? sdfv[tid * 2 + 1] : 0.f;
    }
    __syncthreads();

    for (int iter = 0; iter < 10; ++iter) {
        if (tid == 0) s_flag = 0;
        __syncthreads();
        if (tid < TRACE_G) {
            float cs = s_unfin_s[tid] ? s_nsdf_s[tid] : 0.f;
            cs = (cs <= SDF_T) ? 0.f : cs;
            float ce = s_unfin_e[tid] ? s_nsdf_e[tid] : 0.f;
            ce = (ce <= SDF_T) ? 0.f : ce;
            int us = s_unfin_s[tid] & (cs > SDF_T);
            int ue = s_unfin_e[tid] & (ce > SDF_T);
            s_unfin_s[tid] = us; s_unfin_e[tid] = ue;
            s_csdf_s[tid] = cs; s_csdf_e[tid] = ce;
            s_acc_s[tid] += cs;
            s_acc_e[tid] -= ce;
            if (us | ue) s_flag = 1;   // benign race, all write 1
        }
        __syncthreads();
        if (!s_flag) break;            // exact: state is invariant once all finished

        // round A: sdf at advanced points
        if (tid < TRACE_P) {
            int g = tid >> 1;
            float a = (tid & 1) ? s_acc_e[g] : s_acc_s[g];
            pts[tid * 3 + 0] = fmaf(a, s_ray[g][0], s_cam[g][0]);
            pts[tid * 3 + 1] = fmaf(a, s_ray[g][1], s_cam[g][1]);
            pts[tid * 3 + 2] = fmaf(a, s_ray[g][2], s_cam[g][2]);
        }
        __syncthreads();
        sdf_eval<TRACE_P>(W1, b1, W2, b2, W3, b3v, pts, h1s, red, sdfv);
        if (tid == 0) s_flag = 0;
        __syncthreads();
        if (tid < TRACE_G) {
            float ns = s_unfin_s[tid] ? sdfv[tid * 2 + 0] : 0.f;
            float ne = s_unfin_e[tid] ? sdfv[tid * 2 + 1] : 0.f;
            int nps = (ns < 0.f) ? 1 : 0;
            int npe = (ne < 0.f) ? 1 : 0;
            s_nsdf_s[tid] = ns; s_nsdf_e[tid] = ne;
            s_np_s[tid] = nps; s_np_e[tid] = npe;
            if (nps) s_acc_s[tid] -= 0.5f * s_csdf_s[tid];   // (1-LINE_SEARCH_STEP)/2^0
            if (npe) s_acc_e[tid] += 0.5f * s_csdf_e[tid];
            if (nps | npe) s_flag = 1;
        }
        __syncthreads();
        if (s_flag) {
            // round B: line-search re-eval (identical value where np==false)
            if (tid < TRACE_P) {
                int g = tid >> 1;
                float a = (tid & 1) ? s_acc_e[g] : s_acc_s[g];
                pts[tid * 3 + 0] = fmaf(a, s_ray[g][0], s_cam[g][0]);
                pts[tid * 3 + 1] = fmaf(a, s_ray[g][1], s_cam[g][1]);
                pts[tid * 3 + 2] = fmaf(a, s_ray[g][2], s_cam[g][2]);
            }
            __syncthreads();
            sdf_eval<TRACE_P>(W1, b1, W2, b2, W3, b3v, pts, h1s, red, sdfv);
            if (tid < TRACE_G) {
                if (s_np_s[tid]) s_nsdf_s[tid] = sdfv[tid * 2 + 0];
                if (s_np_e[tid]) s_nsdf_e[tid] = sdfv[tid * 2 + 1];
            }
            __syncthreads();
        }
        if (tid < TRACE_G) {
            int lt = (s_acc_s[tid] < s_acc_e[tid]) ? 1 : 0;
            s_unfin_s[tid] &= lt;
            s_unfin_e[tid] &= lt;
        }
        __syncthreads();
    }

    // final refinement + default outputs
    if (tid < TRACE_G) {
        int r = rbase + tid;
        if (r < R) {
            float cs = s_unfin_s[tid] ? s_nsdf_s[tid] : 0.f;
            cs = (cs <= SDF_T) ? 0.f : cs;
            int mask = s_unfin_s[tid] & ((cs > SDF_T) ? 1 : 0);
            g_mask[r] = mask;
            g_smin[r] = s_acc_s[tid];
            g_smax[r] = s_acc_e[tid];
            float as = s_acc_s[tid];
            out[r * 3 + 0] = fmaf(as, s_ray[tid][0], s_cam[tid][0]);
            out[r * 3 + 1] = fmaf(as, s_ray[tid][1], s_cam[tid][1]);
            out[r * 3 + 2] = fmaf(as, s_ray[tid][2], s_cam[tid][2]);
            out[R * 3 + r] = (as < s_acc_e[tid]) ? 1.f : 0.f;  // net_obj default
            out[R * 4 + r] = as;                               // dists default
        }
    }
}

// ---------------- kernel 2: uniform sampler + secant (masked rays only) ----------------
__global__ __launch_bounds__(256)
void sampler_kernel(
    const float* __restrict__ cam_in, const float* __restrict__ ray_in,
    const float* __restrict__ W1, const float* __restrict__ b1,
    const float* __restrict__ W2, const float* __restrict__ b2,
    const float* __restrict__ W3, const float* __restrict__ b3,
    float* __restrict__ out, int R)
{
    const int r = blockIdx.x;
    if (g_mask[r] == 0) return;   // uniform early-exit, before any sync

    __shared__ float h1s[256 * SAMP_P];
    __shared__ float red[8 * SAMP_P];
    __shared__ float pts[SAMP_P * 3];
    __shared__ float sdfv[SAMP_P];
    __shared__ float sdf100[100];
    __shared__ float s_cr[6];      // cam(3), ray(3)
    __shared__ float st[5];        // zlo, zhi, slo, shi, zpred
    __shared__ int   st_i[2];      // ind, net_surface

    const int tid = threadIdx.x;
    const float b3v = b3[0];
    if (tid < 6)
        s_cr[tid] = (tid < 3) ? cam_in[r * 3 + tid] : ray_in[r * 3 + tid - 3];
    const float smin = g_smin[r];
    const float smax = g_smax[r];
    const float dz = smax - smin;
    __syncthreads();

    // 5 rounds x 20 samples = 100 sdf evals
    for (int round = 0; round < 5; ++round) {
        if (tid < SAMP_P) {
            int i = round * SAMP_P + tid;
            float z = fmaf(dz, (float)i * INV99, smin);
            pts[tid * 3 + 0] = fmaf(z, s_cr[3], s_cr[0]);
            pts[tid * 3 + 1] = fmaf(z, s_cr[4], s_cr[1]);
            pts[tid * 3 + 2] = fmaf(z, s_cr[5], s_cr[2]);
        }
        __syncthreads();
        sdf_eval<SAMP_P>(W1, b1, W2, b2, W3, b3v, pts, h1s, red, sdfv);
        if (tid < SAMP_P) sdf100[round * SAMP_P + tid] = sdfv[tid];
        __syncthreads();
    }

    // first sign transition: argmin of sign(sdf)*(100-i), first occurrence
    if (tid == 0) {
        float best = 3.0e38f; int ind = 0;
        for (int i = 0; i < 100; ++i) {
            float s = sdf100[i];
            float sg = (s > 0.f) ? 1.f : ((s < 0.f) ? -1.f : 0.f);
            float t = sg * (float)(100 - i);
            if (t < best) { best = t; ind = i; }
        }
        int il = (ind + 99) % 100;     // torch's (ind-1) wrap
        float zlo = fmaf(dz, (float)il  * INV99, smin);
        float zhi = fmaf(dz, (float)ind * INV99, smin);
        float slo = sdf100[il], shi = sdf100[ind];
        float den = shi - slo; if (fabsf(den) <= 1e-12f) den = 1e-12f;
        float zp = -slo * (zhi - zlo) / den + zlo;
        st[0] = zlo; st[1] = zhi; st[2] = slo; st[3] = shi; st[4] = zp;
        st_i[0] = ind;
        st_i[1] = (shi < 0.f) ? 1 : 0;
    }
    __syncthreads();

    // secant refinement (result only used when net_surface — skip exactly otherwise)
    if (st_i[1]) {
        for (int it = 0; it < 8; ++it) {
            if (tid < 4) {
                float zp = st[4];
                pts[tid * 3 + 0] = fmaf(zp, s_cr[3], s_cr[0]);
                pts[tid * 3 + 1] = fmaf(zp, s_cr[4], s_cr[1]);
                pts[tid * 3 + 2] = fmaf(zp, s_cr[5], s_cr[2]);
            }
            __syncthreads();
            sdf_eval<4>(W1, b1, W2, b2, W3, b3v, pts, h1s, red, sdfv);
            if (tid == 0) {
                float mid = sdfv[0];
                if (mid > 0.f) { st[0] = st[4]; st[2] = mid; }
                if (mid < 0.f) { st[1] = st[4]; st[3] = mid; }
                float den = st[3] - st[2]; if (fabsf(den) <= 1e-12f) den = 1e-12f;
                st[4] = -st[2] * (st[1] - st[0]) / den + st[0];
            }
            __syncthreads();
        }
    }

    if (tid == 0) {
        int ns = st_i[1];
        float dist = ns ? st[4]
                        : fmaf(dz, (float)st_i[0] * INV99, smin);
        out[r * 3 + 0] = fmaf(dist, s_cr[3], s_cr[0]);
        out[r * 3 + 1] = fmaf(dist, s_cr[4], s_cr[1]);
        out[r * 3 + 2] = fmaf(dist, s_cr[5], s_cr[2]);
        out[R * 3 + r] = ns ? 1.f : 0.f;   // net_obj := net_surface on masked rays
        out[R * 4 + r] = dist;
    }
}

// ---------------- launch ----------------
extern "C" void kernel_launch(void* const* d_in, const int* in_sizes, int n_in,
                              void* d_out, int out_size)
{
    const float* cam  = (const float*)d_in[0];
    const float* rays = (const float*)d_in[1];
    // d_in[2] = object_mask (unused by the eval-mode forward)
    const float* W1 = (const float*)d_in[3];
    const float* b1 = (const float*)d_in[4];
    const float* W2 = (const float*)d_in[5];
    const float* b2 = (const float*)d_in[6];
    const float* W3 = (const float*)d_in[7];
    const float* b3 = (const float*)d_in[8];
    int R = in_sizes[0] / 3;
    if (R > RMAX) R = RMAX;
    float* out = (float*)d_out;

    int nb = (R + TRACE_G - 1) / TRACE_G;
    trace_kernel<<<nb, 256>>>(cam, rays, W1, b1, W2, b2, W3, b3, out, R);
    sampler_kernel<<<R, 256>>>(cam, rays, W1, b1, W2, b2, W3, b3, out, R);
}

// round 2
// speedup vs baseline: 1.2396x; 1.2396x over previous
#include <cuda_runtime.h>
#include <math.h>

// ---------------- constants ----------------
#define RMAX 8192
static constexpr float SDF_T = 5e-05f;
static constexpr int   TRACE_G = 8;    // rays per trace block
static constexpr int   TRACE_P = 16;   // points per eval round (2*G)
static constexpr int   SAMP_P  = 20;   // points per sampler round (5 rounds = 100)
static constexpr int   SEC_G   = 16;   // rays per secant block
static constexpr float INV99   = 1.0f / 99.0f;

// inter-kernel scratch (no allocations allowed)
__device__ float g_smin[RMAX];
__device__ float g_smax[RMAX];
__device__ int   g_mask[RMAX];
__device__ int   g_seclist[RMAX];
__device__ int   g_seccount;
__device__ float g_zlo[RMAX], g_zhi[RMAX], g_slo[RMAX], g_shi[RMAX], g_zp[RMAX];

__global__ void init_kernel() { g_seccount = 0; }

// ---------------- batched SDF eval ----------------
// Evaluates sdf(p) for P points (P % 4 == 0). All 256 threads participate.
// pts:  P*3 floats in smem ; h1s: 256*P floats (k-major) ; red: 8*P ; sdfv: P
template<int P>
__device__ __forceinline__ void sdf_eval(
    const float* __restrict__ W1, const float* __restrict__ b1,
    const float* __restrict__ W2, const float* __restrict__ b2,
    const float* __restrict__ W3, float b3v,
    const float* pts, float* h1s, float* red, float* sdfv)
{
    const int tid = threadIdx.x;

    // ---- layer 1: h1[k][p] = tanh(p . W1[:,k] + b1[k]) ----
#pragma unroll
    for (int it = 0; it < P; ++it) {
        int idx = it * 256 + tid;       // coalesced writes
        int k = idx / P;
        int p = idx - k * P;
        float x = pts[p * 3 + 0], y = pts[p * 3 + 1], z = pts[p * 3 + 2];
        float v = fmaf(W1[k], x, fmaf(W1[256 + k], y, fmaf(W1[512 + k], z, b1[k])));
        h1s[idx] = tanhf(v);
    }
    __syncthreads();

    // ---- layer 2: thread j owns neuron j; software-pipelined W2 loads ----
    constexpr int P4 = P / 4;
    float4 acc4[P4];
#pragma unroll
    for (int q = 0; q < P4; ++q) acc4[q] = make_float4(0.f, 0.f, 0.f, 0.f);

    const float* W2j = W2 + tid;
    float w[8];
#pragma unroll
    for (int u = 0; u < 8; ++u) w[u] = W2j[u * 256];

#pragma unroll 1
    for (int k0 = 0; k0 < 256; k0 += 8) {
        float wn[8];
        if (k0 + 8 < 256) {
#pragma unroll
            for (int u = 0; u < 8; ++u) wn[u] = W2j[(k0 + 8 + u) * 256];
        } else {
#pragma unroll
            for (int u = 0; u < 8; ++u) wn[u] = 0.f;
        }
#pragma unroll
        for (int u = 0; u < 8; ++u) {
            const float4* h4 = reinterpret_cast<const float4*>(h1s + (k0 + u) * P);
#pragma unroll
            for (int q = 0; q < P4; ++q) {
                float4 v = h4[q];                    // broadcast LDS.128
                acc4[q].x = fmaf(v.x, w[u], acc4[q].x);
                acc4[q].y = fmaf(v.y, w[u], acc4[q].y);
                acc4[q].z = fmaf(v.z, w[u], acc4[q].z);
                acc4[q].w = fmaf(v.w, w[u], acc4[q].w);
            }
        }
#pragma unroll
        for (int u = 0; u < 8; ++u) w[u] = wn[u];
    }

    // ---- layer 3 ----
    const float bb2 = b2[tid];
    const float w3j = W3[tid];
#pragma unroll
    for (int q = 0; q < P4; ++q) {
        float a[4] = {acc4[q].x, acc4[q].y, acc4[q].z, acc4[q].w};
#pragma unroll
        for (int c = 0; c < 4; ++c) {
            int p = q * 4 + c;
            float m = tanhf(a[c] + bb2) * w3j;
#pragma unroll
            for (int off = 16; off; off >>= 1)
                m += __shfl_down_sync(0xffffffffu, m, off);
            if ((tid & 31) == 0) red[p * 8 + (tid >> 5)] = m;
        }
    }
    __syncthreads();
    if (tid < P) {
        float s = 0.f;
#pragma unroll
        for (int q = 0; q < 8; ++q) s += red[tid * 8 + q];
        float x = pts[tid * 3 + 0], y = pts[tid * 3 + 1], z = pts[tid * 3 + 2];
        float base = sqrtf(fmaf(x, x, fmaf(y, y, fmaf(z, z, 1e-12f)))) - 0.6f;
        sdfv[tid] = base + 0.05f * (s + b3v);
    }
    __syncthreads();
}

// ---------------- kernel 1: init + sphere tracing ----------------
__global__ __launch_bounds__(256, 3)
void trace_kernel(
    const float* __restrict__ cam_in, const float* __restrict__ ray_in,
    const float* __restrict__ W1, const float* __restrict__ b1,
    const float* __restrict__ W2, const float* __restrict__ b2,
    const float* __restrict__ W3, const float* __restrict__ b3,
    float* __restrict__ out, int R)
{
    __shared__ float h1s[256 * TRACE_P];
    __shared__ float red[8 * TRACE_P];
    __shared__ float pts[TRACE_P * 3];
    __shared__ float sdfv[TRACE_P];
    __shared__ float s_cam[TRACE_G][3], s_ray[TRACE_G][3];
    __shared__ float s_acc_s[TRACE_G], s_acc_e[TRACE_G];
    __shared__ float s_nsdf_s[TRACE_G], s_nsdf_e[TRACE_G];
    __shared__ float s_csdf_s[TRACE_G], s_csdf_e[TRACE_G];
    __shared__ int   s_unfin_s[TRACE_G], s_unfin_e[TRACE_G];
    __shared__ int   s_np_s[TRACE_G], s_np_e[TRACE_G];
    __shared__ int   s_flag;

    const int tid   = threadIdx.x;
    const int rbase = blockIdx.x * TRACE_G;
    const float b3v = b3[0];

    if (tid < TRACE_G) {
        int r = rbase + tid;
        float cx = 0.f, cy = 0.f, cz = 0.f, rx = 0.f, ry = 0.f, rz = 0.f;
        bool valid = (r < R);
        if (valid) {
            cx = cam_in[r * 3 + 0]; cy = cam_in[r * 3 + 1]; cz = cam_in[r * 3 + 2];
            rx = ray_in[r * 3 + 0]; ry = ray_in[r * 3 + 1]; rz = ray_in[r * 3 + 2];
        }
        s_cam[tid][0] = cx; s_cam[tid][1] = cy; s_cam[tid][2] = cz;
        s_ray[tid][0] = rx; s_ray[tid][1] = ry; s_ray[tid][2] = rz;
        float dt = rx * cx + ry * cy + rz * cz;
        float cc = cx * cx + cy * cy + cz * cz;
        float under = dt * dt - (cc - 1.0f);
        bool mi = valid && (under > 0.f);
        float sq = sqrtf(mi ? under : 1.0f);
        float i0 = mi ? fmaxf(-sq - dt, 0.f) : 0.f;
        float i1 = mi ? fmaxf( sq - dt, 0.f) : 0.f;
        s_acc_s[tid] = i0; s_acc_e[tid] = i1;
        s_unfin_s[tid] = mi ? 1 : 0;
        s_unfin_e[tid] = mi ? 1 : 0;
    }
    __syncthreads();

    // round 0: initial sdf at both endpoints
    if (tid < TRACE_P) {
        int g = tid >> 1;
        float a = (tid & 1) ? s_acc_e[g] : s_acc_s[g];
        pts[tid * 3 + 0] = fmaf(a, s_ray[g][0], s_cam[g][0]);
        pts[tid * 3 + 1] = fmaf(a, s_ray[g][1], s_cam[g][1]);
        pts[tid * 3 + 2] = fmaf(a, s_ray[g][2], s_cam[g][2]);
    }
    __syncthreads();
    sdf_eval<TRACE_P>(W1, b1, W2, b2, W3, b3v, pts, h1s, red, sdfv);
    if (tid < TRACE_G) {
        s_nsdf_s[tid] = s_unfin_s[tid] ? sdfv[tid * 2 + 0] : 0.f;
        s_nsdf_e[tid] = s_unfin_e[tid] ? sdfv[tid * 2 + 1] : 0.f;
    }
    __syncthreads();

    for (int iter = 0; iter < 10; ++iter) {
        if (tid == 0) s_flag = 0;
        __syncthreads();
        if (tid < TRACE_G) {
            float cs = s_unfin_s[tid] ? s_nsdf_s[tid] : 0.f;
            cs = (cs <= SDF_T) ? 0.f : cs;
            float ce = s_unfin_e[tid] ? s_nsdf_e[tid] : 0.f;
            ce = (ce <= SDF_T) ? 0.f : ce;
            int us = s_unfin_s[tid] & (cs > SDF_T);
            int ue = s_unfin_e[tid] & (ce > SDF_T);
            s_unfin_s[tid] = us; s_unfin_e[tid] = ue;
            s_csdf_s[tid] = cs; s_csdf_e[tid] = ce;
            s_acc_s[tid] += cs;
            s_acc_e[tid] -= ce;
            if (us | ue) s_flag = 1;   // benign race, all write 1
        }
        __syncthreads();
        if (!s_flag) break;            // exact: state invariant once all finished

        if (tid < TRACE_P) {
            int g = tid >> 1;
            float a = (tid & 1) ? s_acc_e[g] : s_acc_s[g];
            pts[tid * 3 + 0] = fmaf(a, s_ray[g][0], s_cam[g][0]);
            pts[tid * 3 + 1] = fmaf(a, s_ray[g][1], s_cam[g][1]);
            pts[tid * 3 + 2] = fmaf(a, s_ray[g][2], s_cam[g][2]);
        }
        __syncthreads();
        sdf_eval<TRACE_P>(W1, b1, W2, b2, W3, b3v, pts, h1s, red, sdfv);
        if (tid == 0) s_flag = 0;
        __syncthreads();
        if (tid < TRACE_G) {
            float ns = s_unfin_s[tid] ? sdfv[tid * 2 + 0] : 0.f;
            float ne = s_unfin_e[tid] ? sdfv[tid * 2 + 1] : 0.f;
            int nps = (ns < 0.f) ? 1 : 0;
            int npe = (ne < 0.f) ? 1 : 0;
            s_nsdf_s[tid] = ns; s_nsdf_e[tid] = ne;
            s_np_s[tid] = nps; s_np_e[tid] = npe;
            if (nps) s_acc_s[tid] -= 0.5f * s_csdf_s[tid];
            if (npe) s_acc_e[tid] += 0.5f * s_csdf_e[tid];
            if (nps | npe) s_flag = 1;
        }
        __syncthreads();
        if (s_flag) {
            if (tid < TRACE_P) {
                int g = tid >> 1;
                float a = (tid & 1) ? s_acc_e[g] : s_acc_s[g];
                pts[tid * 3 + 0] = fmaf(a, s_ray[g][0], s_cam[g][0]);
                pts[tid * 3 + 1] = fmaf(a, s_ray[g][1], s_cam[g][1]);
                pts[tid * 3 + 2] = fmaf(a, s_ray[g][2], s_cam[g][2]);
            }
            __syncthreads();
            sdf_eval<TRACE_P>(W1, b1, W2, b2, W3, b3v, pts, h1s, red, sdfv);
            if (tid < TRACE_G) {
                if (s_np_s[tid]) s_nsdf_s[tid] = sdfv[tid * 2 + 0];
                if (s_np_e[tid]) s_nsdf_e[tid] = sdfv[tid * 2 + 1];
            }
            __syncthreads();
        }
        if (tid < TRACE_G) {
            int lt = (s_acc_s[tid] < s_acc_e[tid]) ? 1 : 0;
            s_unfin_s[tid] &= lt;
            s_unfin_e[tid] &= lt;
        }
        __syncthreads();
    }

    if (tid < TRACE_G) {
        int r = rbase + tid;
        if (r < R) {
            float cs = s_unfin_s[tid] ? s_nsdf_s[tid] : 0.f;
            cs = (cs <= SDF_T) ? 0.f : cs;
            int mask = s_unfin_s[tid] & ((cs > SDF_T) ? 1 : 0);
            g_mask[r] = mask;
            g_smin[r] = s_acc_s[tid];
            g_smax[r] = s_acc_e[tid];
            float as = s_acc_s[tid];
            out[r * 3 + 0] = fmaf(as, s_ray[tid][0], s_cam[tid][0]);
            out[r * 3 + 1] = fmaf(as, s_ray[tid][1], s_cam[tid][1]);
            out[r * 3 + 2] = fmaf(as, s_ray[tid][2], s_cam[tid][2]);
            out[R * 3 + r] = (as < s_acc_e[tid]) ? 1.f : 0.f;
            out[R * 4 + r] = as;
        }
    }
}

// ---------------- kernel 2: uniform sampler (masked rays only) ----------------
__global__ __launch_bounds__(256, 3)
void sampler_kernel(
    const float* __restrict__ cam_in, const float* __restrict__ ray_in,
    const float* __restrict__ W1, const float* __restrict__ b1,
    const float* __restrict__ W2, const float* __restrict__ b2,
    const float* __restrict__ W3, const float* __restrict__ b3,
    float* __restrict__ out, int R)
{
    const int r = blockIdx.x;
    if (g_mask[r] == 0) return;   // uniform early-exit, before any sync

    __shared__ float h1s[256 * SAMP_P];
    __shared__ float red[8 * SAMP_P];
    __shared__ float pts[SAMP_P * 3];
    __shared__ float sdfv[SAMP_P];
    __shared__ float sdf100[100];
    __shared__ float s_cr[6];

    const int tid = threadIdx.x;
    const float b3v = b3[0];
    if (tid < 6)
        s_cr[tid] = (tid < 3) ? cam_in[r * 3 + tid] : ray_in[r * 3 + tid - 3];
    const float smin = g_smin[r];
    const float smax = g_smax[r];
    const float dz = smax - smin;
    __syncthreads();

    for (int round = 0; round < 5; ++round) {
        if (tid < SAMP_P) {
            int i = round * SAMP_P + tid;
            float z = fmaf(dz, (float)i * INV99, smin);
            pts[tid * 3 + 0] = fmaf(z, s_cr[3], s_cr[0]);
            pts[tid * 3 + 1] = fmaf(z, s_cr[4], s_cr[1]);
            pts[tid * 3 + 2] = fmaf(z, s_cr[5], s_cr[2]);
        }
        __syncthreads();
        sdf_eval<SAMP_P>(W1, b1, W2, b2, W3, b3v, pts, h1s, red, sdfv);
        if (tid < SAMP_P) sdf100[round * SAMP_P + tid] = sdfv[tid];
        __syncthreads();
    }

    // first sign transition + secant bracket
    if (tid == 0) {
        float best = 3.0e38f; int ind = 0;
        for (int i = 0; i < 100; ++i) {
            float s = sdf100[i];
            float sg = (s > 0.f) ? 1.f : ((s < 0.f) ? -1.f : 0.f);
            float t = sg * (float)(100 - i);
            if (t < best) { best = t; ind = i; }
        }
        int il = (ind + 99) % 100;     // torch's (ind-1) wrap
        float zlo = fmaf(dz, (float)il  * INV99, smin);
        float zhi = fmaf(dz, (float)ind * INV99, smin);
        float slo = sdf100[il], shi = sdf100[ind];
        if (shi < 0.f) {
            // net_surface ray -> defer to batched secant kernel
            float den = shi - slo; if (fabsf(den) <= 1e-12f) den = 1e-12f;
            float zp = -slo * (zhi - zlo) / den + zlo;
            g_zlo[r] = zlo; g_zhi[r] = zhi; g_slo[r] = slo; g_shi[r] = shi; g_zp[r] = zp;
            int pos = atomicAdd(&g_seccount, 1);
            g_seclist[pos] = r;
        } else {
            float dist = zhi;          // s_dists = z_vals[ind]
            out[r * 3 + 0] = fmaf(dist, s_cr[3], s_cr[0]);
            out[r * 3 + 1] = fmaf(dist, s_cr[4], s_cr[1]);
            out[r * 3 + 2] = fmaf(dist, s_cr[5], s_cr[2]);
            out[R * 3 + r] = 0.f;      // net_surface false
            out[R * 4 + r] = dist;
        }
    }
}

// ---------------- kernel 3: batched secant (net_surface rays) ----------------
__global__ __launch_bounds__(256, 3)
void secant_kernel(
    const float* __restrict__ cam_in, const float* __restrict__ ray_in,
    const float* __restrict__ W1, const float* __restrict__ b1,
    const float* __restrict__ W2, const float* __restrict__ b2,
    const float* __restrict__ W3, const float* __restrict__ b3,
    float* __restrict__ out, int R)
{
    const int base = blockIdx.x * SEC_G;
    if (base >= g_seccount) return;   // uniform exit before any sync

    __shared__ float h1s[256 * SEC_G];
    __shared__ float red[8 * SEC_G];
    __shared__ float pts[SEC_G * 3];
    __shared__ float sdfv[SEC_G];
    __shared__ float s_cr[SEC_G][6];
    __shared__ float s_zlo[SEC_G], s_zhi[SEC_G], s_slo[SEC_G], s_shi[SEC_G], s_zp[SEC_G];
    __shared__ int   s_r[SEC_G];
    __shared__ int   s_n;

    const int tid = threadIdx.x;
    const float b3v = b3[0];
    if (tid == 0) {
        int c = g_seccount - base;
        s_n = (c < SEC_G) ? c : SEC_G;
    }
    __syncthreads();
    const int n = s_n;
    if (tid < SEC_G) {
        int li = (tid < n) ? tid : 0;
        int r = g_seclist[base + li];
        s_r[tid] = (tid < n) ? r : -1;
        s_zlo[tid] = g_zlo[r]; s_zhi[tid] = g_zhi[r];
        s_slo[tid] = g_slo[r]; s_shi[tid] = g_shi[r];
        s_zp[tid]  = g_zp[r];
        s_cr[tid][0] = cam_in[r * 3 + 0]; s_cr[tid][1] = cam_in[r * 3 + 1]; s_cr[tid][2] = cam_in[r * 3 + 2];
        s_cr[tid][3] = ray_in[r * 3 + 0]; s_cr[tid][4] = ray_in[r * 3 + 1]; s_cr[tid][5] = ray_in[r * 3 + 2];
    }
    __syncthreads();

    for (int it = 0; it < 8; ++it) {
        if (tid < SEC_G) {
            float zp = s_zp[tid];
            pts[tid * 3 + 0] = fmaf(zp, s_cr[tid][3], s_cr[tid][0]);
            pts[tid * 3 + 1] = fmaf(zp, s_cr[tid][4], s_cr[tid][1]);
            pts[tid * 3 + 2] = fmaf(zp, s_cr[tid][5], s_cr[tid][2]);
        }
        __syncthreads();
        sdf_eval<SEC_G>(W1, b1, W2, b2, W3, b3v, pts, h1s, red, sdfv);
        if (tid < SEC_G) {
            float mid = sdfv[tid];
            if (mid > 0.f) { s_zlo[tid] = s_zp[tid]; s_slo[tid] = mid; }
            if (mid < 0.f) { s_zhi[tid] = s_zp[tid]; s_shi[tid] = mid; }
            float den = s_shi[tid] - s_slo[tid];
            if (fabsf(den) <= 1e-12f) den = 1e-12f;
            s_zp[tid] = -s_slo[tid] * (s_zhi[tid] - s_zlo[tid]) / den + s_zlo[tid];
        }
        __syncthreads();
    }

    if (tid < n) {
        int r = s_r[tid];
        float dist = s_zp[tid];
        out[r * 3 + 0] = fmaf(dist, s_cr[tid][3], s_cr[tid][0]);
        out[r * 3 + 1] = fmaf(dist, s_cr[tid][4], s_cr[tid][1]);
        out[r * 3 + 2] = fmaf(dist, s_cr[tid][5], s_cr[tid][2]);
        out[R * 3 + r] = 1.f;          // net_surface true
        out[R * 4 + r] = dist;
    }
}

// ---------------- launch ----------------
extern "C" void kernel_launch(void* const* d_in, const int* in_sizes, int n_in,
                              void* d_out, int out_size)
{
    const float* cam  = (const float*)d_in[0];
    const float* rays = (const float*)d_in[1];
    // d_in[2] = object_mask (unused by the eval-mode forward)
    const float* W1 = (const float*)d_in[3];
    const float* b1 = (const float*)d_in[4];
    const float* W2 = (const float*)d_in[5];
    const float* b2 = (const float*)d_in[6];
    const float* W3 = (const float*)d_in[7];
    const float* b3 = (const float*)d_in[8];
    int R = in_sizes[0] / 3;
    if (R > RMAX) R = RMAX;
    float* out = (float*)d_out;

    init_kernel<<<1, 1>>>();
    int nb = (R + TRACE_G - 1) / TRACE_G;
    trace_kernel<<<nb, 256>>>(cam, rays, W1, b1, W2, b2, W3, b3, out, R);
    sampler_kernel<<<R, 256>>>(cam, rays, W1, b1, W2, b2, W3, b3, out, R);
    int sb = (R + SEC_G - 1) / SEC_G;
    secant_kernel<<<sb, 256>>>(cam, rays, W1, b1, W2, b2, W3, b3, out, R);
}

// round 3
// speedup vs baseline: 1.3029x; 1.0511x over previous
#include <cuda_runtime.h>
#include <math.h>

// ---------------- constants ----------------
#define RMAX 8192
static constexpr float SDF_T = 5e-05f;
static constexpr int   TRACE_G = 8;    // rays per trace block
static constexpr int   TRACE_P = 16;   // points per eval round (2*G)
static constexpr int   SAMP_P  = 20;   // points per sampler block
static constexpr int   SEC_G   = 8;    // rays per secant block
static constexpr float INV99   = 1.0f / 99.0f;

// inter-kernel scratch (no allocations allowed)
__device__ float g_smin[RMAX];
__device__ float g_smax[RMAX];
__device__ int   g_mlist[RMAX];
__device__ int   g_nmasked;
__device__ int   g_seclist[RMAX];
__device__ int   g_seccount;
__device__ float g_zlo[RMAX], g_zhi[RMAX], g_slo[RMAX], g_shi[RMAX], g_zp[RMAX];
__device__ float g_sdf[RMAX * 100];

__global__ void init_kernel() { g_nmasked = 0; g_seccount = 0; }

// ---------------- batched SDF eval ----------------
// Evaluates sdf(p) for P points (P % 4 == 0). All 256 threads participate.
// Depth-2 software pipeline on W2 global loads (covers L2 latency).
template<int P>
__device__ __forceinline__ void sdf_eval(
    const float* __restrict__ W1, const float* __restrict__ b1,
    const float* __restrict__ W2, const float* __restrict__ b2,
    const float* __restrict__ W3, float b3v,
    const float* pts, float* h1s, float* red, float* sdfv)
{
    const int tid = threadIdx.x;

    // ---- layer 1: h1[k][p] = tanh(p . W1[:,k] + b1[k]) ----
#pragma unroll
    for (int it = 0; it < P; ++it) {
        int idx = it * 256 + tid;       // coalesced writes
        int k = idx / P;
        int p = idx - k * P;
        float x = pts[p * 3 + 0], y = pts[p * 3 + 1], z = pts[p * 3 + 2];
        float v = fmaf(W1[k], x, fmaf(W1[256 + k], y, fmaf(W1[512 + k], z, b1[k])));
        h1s[idx] = tanhf(v);
    }
    __syncthreads();

    // ---- layer 2: thread j owns neuron j; depth-2 pipelined W2 loads ----
    constexpr int P4 = P / 4;
    float4 acc4[P4];
#pragma unroll
    for (int q = 0; q < P4; ++q) acc4[q] = make_float4(0.f, 0.f, 0.f, 0.f);

    const float* W2j = W2 + tid;
    float w0[8], w1[8];
#pragma unroll
    for (int u = 0; u < 8; ++u) w0[u] = W2j[u * 256];
#pragma unroll
    for (int u = 0; u < 8; ++u) w1[u] = W2j[(8 + u) * 256];

#pragma unroll 1
    for (int k0 = 0; k0 < 256; k0 += 8) {
        float wn[8];
        int kp = k0 + 16;
        if (kp < 256) {
#pragma unroll
            for (int u = 0; u < 8; ++u) wn[u] = W2j[(kp + u) * 256];
        } else {
#pragma unroll
            for (int u = 0; u < 8; ++u) wn[u] = 0.f;
        }
#pragma unroll
        for (int u = 0; u < 8; ++u) {
            const float4* h4 = reinterpret_cast<const float4*>(h1s + (k0 + u) * P);
#pragma unroll
            for (int q = 0; q < P4; ++q) {
                float4 v = h4[q];                    // broadcast LDS.128
                acc4[q].x = fmaf(v.x, w0[u], acc4[q].x);
                acc4[q].y = fmaf(v.y, w0[u], acc4[q].y);
                acc4[q].z = fmaf(v.z, w0[u], acc4[q].z);
                acc4[q].w = fmaf(v.w, w0[u], acc4[q].w);
            }
        }
#pragma unroll
        for (int u = 0; u < 8; ++u) { w0[u] = w1[u]; w1[u] = wn[u]; }
    }

    // ---- layer 3 ----
    const float bb2 = b2[tid];
    const float w3j = W3[tid];
#pragma unroll
    for (int q = 0; q < P4; ++q) {
        float a[4] = {acc4[q].x, acc4[q].y, acc4[q].z, acc4[q].w};
#pragma unroll
        for (int c = 0; c < 4; ++c) {
            int p = q * 4 + c;
            float m = tanhf(a[c] + bb2) * w3j;
#pragma unroll
            for (int off = 16; off; off >>= 1)
                m += __shfl_down_sync(0xffffffffu, m, off);
            if ((tid & 31) == 0) red[p * 8 + (tid >> 5)] = m;
        }
    }
    __syncthreads();
    if (tid < P) {
        float s = 0.f;
#pragma unroll
        for (int q = 0; q < 8; ++q) s += red[tid * 8 + q];
        float x = pts[tid * 3 + 0], y = pts[tid * 3 + 1], z = pts[tid * 3 + 2];
        float base = sqrtf(fmaf(x, x, fmaf(y, y, fmaf(z, z, 1e-12f)))) - 0.6f;
        sdfv[tid] = base + 0.05f * (s + b3v);
    }
    __syncthreads();
}

// ---------------- kernel 1: init + sphere tracing ----------------
__global__ __launch_bounds__(256, 4)
void trace_kernel(
    const float* __restrict__ cam_in, const float* __restrict__ ray_in,
    const float* __restrict__ W1, const float* __restrict__ b1,
    const float* __restrict__ W2, const float* __restrict__ b2,
    const float* __restrict__ W3, const float* __restrict__ b3,
    float* __restrict__ out, int R)
{
    __shared__ float h1s[256 * TRACE_P];
    __shared__ float red[8 * TRACE_P];
    __shared__ float pts[TRACE_P * 3];
    __shared__ float sdfv[TRACE_P];
    __shared__ float s_cam[TRACE_G][3], s_ray[TRACE_G][3];
    __shared__ float s_acc_s[TRACE_G], s_acc_e[TRACE_G];
    __shared__ float s_nsdf_s[TRACE_G], s_nsdf_e[TRACE_G];
    __shared__ float s_csdf_s[TRACE_G], s_csdf_e[TRACE_G];
    __shared__ int   s_unfin_s[TRACE_G], s_unfin_e[TRACE_G];
    __shared__ int   s_np_s[TRACE_G], s_np_e[TRACE_G];
    __shared__ int   s_flag;

    const int tid   = threadIdx.x;
    const int rbase = blockIdx.x * TRACE_G;
    const float b3v = b3[0];

    if (tid < TRACE_G) {
        int r = rbase + tid;
        float cx = 0.f, cy = 0.f, cz = 0.f, rx = 0.f, ry = 0.f, rz = 0.f;
        bool valid = (r < R);
        if (valid) {
            cx = cam_in[r * 3 + 0]; cy = cam_in[r * 3 + 1]; cz = cam_in[r * 3 + 2];
            rx = ray_in[r * 3 + 0]; ry = ray_in[r * 3 + 1]; rz = ray_in[r * 3 + 2];
        }
        s_cam[tid][0] = cx; s_cam[tid][1] = cy; s_cam[tid][2] = cz;
        s_ray[tid][0] = rx; s_ray[tid][1] = ry; s_ray[tid][2] = rz;
        float dt = rx * cx + ry * cy + rz * cz;
        float cc = cx * cx + cy * cy + cz * cz;
        float under = dt * dt - (cc - 1.0f);
        bool mi = valid && (under > 0.f);
        float sq = sqrtf(mi ? under : 1.0f);
        float i0 = mi ? fmaxf(-sq - dt, 0.f) : 0.f;
        float i1 = mi ? fmaxf( sq - dt, 0.f) : 0.f;
        s_acc_s[tid] = i0; s_acc_e[tid] = i1;
        s_unfin_s[tid] = mi ? 1 : 0;
        s_unfin_e[tid] = mi ? 1 : 0;
    }
    __syncthreads();

    if (tid < TRACE_P) {
        int g = tid >> 1;
        float a = (tid & 1) ? s_acc_e[g] : s_acc_s[g];
        pts[tid * 3 + 0] = fmaf(a, s_ray[g][0], s_cam[g][0]);
        pts[tid * 3 + 1] = fmaf(a, s_ray[g][1], s_cam[g][1]);
        pts[tid * 3 + 2] = fmaf(a, s_ray[g][2], s_cam[g][2]);
    }
    __syncthreads();
    sdf_eval<TRACE_P>(W1, b1, W2, b2, W3, b3v, pts, h1s, red, sdfv);
    if (tid < TRACE_G) {
        s_nsdf_s[tid] = s_unfin_s[tid] ? sdfv[tid * 2 + 0] : 0.f;
        s_nsdf_e[tid] = s_unfin_e[tid] ? sdfv[tid * 2 + 1] : 0.f;
    }
    __syncthreads();

    for (int iter = 0; iter < 10; ++iter) {
        if (tid == 0) s_flag = 0;
        __syncthreads();
        if (tid < TRACE_G) {
            float cs = s_unfin_s[tid] ? s_nsdf_s[tid] : 0.f;
            cs = (cs <= SDF_T) ? 0.f : cs;
            float ce = s_unfin_e[tid] ? s_nsdf_e[tid] : 0.f;
            ce = (ce <= SDF_T) ? 0.f : ce;
            int us = s_unfin_s[tid] & (cs > SDF_T);
            int ue = s_unfin_e[tid] & (ce > SDF_T);
            s_unfin_s[tid] = us; s_unfin_e[tid] = ue;
            s_csdf_s[tid] = cs; s_csdf_e[tid] = ce;
            s_acc_s[tid] += cs;
            s_acc_e[tid] -= ce;
            if (us | ue) s_flag = 1;   // benign race, all write 1
        }
        __syncthreads();
        if (!s_flag) break;            // exact: state invariant once all finished

        if (tid < TRACE_P) {
            int g = tid >> 1;
            float a = (tid & 1) ? s_acc_e[g] : s_acc_s[g];
            pts[tid * 3 + 0] = fmaf(a, s_ray[g][0], s_cam[g][0]);
            pts[tid * 3 + 1] = fmaf(a, s_ray[g][1], s_cam[g][1]);
            pts[tid * 3 + 2] = fmaf(a, s_ray[g][2], s_cam[g][2]);
        }
        __syncthreads();
        sdf_eval<TRACE_P>(W1, b1, W2, b2, W3, b3v, pts, h1s, red, sdfv);
        if (tid == 0) s_flag = 0;
        __syncthreads();
        if (tid < TRACE_G) {
            float ns = s_unfin_s[tid] ? sdfv[tid * 2 + 0] : 0.f;
            float ne = s_unfin_e[tid] ? sdfv[tid * 2 + 1] : 0.f;
            int nps = (ns < 0.f) ? 1 : 0;
            int npe = (ne < 0.f) ? 1 : 0;
            s_nsdf_s[tid] = ns; s_nsdf_e[tid] = ne;
            s_np_s[tid] = nps; s_np_e[tid] = npe;
            if (nps) s_acc_s[tid] -= 0.5f * s_csdf_s[tid];
            if (npe) s_acc_e[tid] += 0.5f * s_csdf_e[tid];
            if (nps | npe) s_flag = 1;
        }
        __syncthreads();
        if (s_flag) {
            if (tid < TRACE_P) {
                int g = tid >> 1;
                float a = (tid & 1) ? s_acc_e[g] : s_acc_s[g];
                pts[tid * 3 + 0] = fmaf(a, s_ray[g][0], s_cam[g][0]);
                pts[tid * 3 + 1] = fmaf(a, s_ray[g][1], s_cam[g][1]);
                pts[tid * 3 + 2] = fmaf(a, s_ray[g][2], s_cam[g][2]);
            }
            __syncthreads();
            sdf_eval<TRACE_P>(W1, b1, W2, b2, W3, b3v, pts, h1s, red, sdfv);
            if (tid < TRACE_G) {
                if (s_np_s[tid]) s_nsdf_s[tid] = sdfv[tid * 2 + 0];
                if (s_np_e[tid]) s_nsdf_e[tid] = sdfv[tid * 2 + 1];
            }
            __syncthreads();
        }
        if (tid < TRACE_G) {
            int lt = (s_acc_s[tid] < s_acc_e[tid]) ? 1 : 0;
            s_unfin_s[tid] &= lt;
            s_unfin_e[tid] &= lt;
        }
        __syncthreads();
    }

    if (tid < TRACE_G) {
        int r = rbase + tid;
        if (r < R) {
            float cs = s_unfin_s[tid] ? s_nsdf_s[tid] : 0.f;
            cs = (cs <= SDF_T) ? 0.f : cs;
            int mask = s_unfin_s[tid] & ((cs > SDF_T) ? 1 : 0);
            g_smin[r] = s_acc_s[tid];
            g_smax[r] = s_acc_e[tid];
            if (mask) {
                int pos = atomicAdd(&g_nmasked, 1);
                g_mlist[pos] = r;
            }
            float as = s_acc_s[tid];
            out[r * 3 + 0] = fmaf(as, s_ray[tid][0], s_cam[tid][0]);
            out[r * 3 + 1] = fmaf(as, s_ray[tid][1], s_cam[tid][1]);
            out[r * 3 + 2] = fmaf(as, s_ray[tid][2], s_cam[tid][2]);
            out[R * 3 + r] = (as < s_acc_e[tid]) ? 1.f : 0.f;
            out[R * 4 + r] = as;
        }
    }
}

// ---------------- kernel 2: fully-parallel uniform sampler ----------------
// grid = R*5 blocks; block b handles masked ray g_mlist[b/5], samples [20*(b%5), +20)
__global__ __launch_bounds__(256, 4)
void samp_eval_kernel(
    const float* __restrict__ cam_in, const float* __restrict__ ray_in,
    const float* __restrict__ W1, const float* __restrict__ b1,
    const float* __restrict__ W2, const float* __restrict__ b2,
    const float* __restrict__ W3, const float* __restrict__ b3)
{
    const int li = blockIdx.x / 5;
    if (li >= g_nmasked) return;      // uniform early-exit, before any sync
    const int round = blockIdx.x - li * 5;
    const int r = g_mlist[li];

    __shared__ float h1s[256 * SAMP_P];
    __shared__ float red[8 * SAMP_P];
    __shared__ float pts[SAMP_P * 3];
    __shared__ float sdfv[SAMP_P];
    __shared__ float s_cr[6];

    const int tid = threadIdx.x;
    const float b3v = b3[0];
    if (tid < 6)
        s_cr[tid] = (tid < 3) ? cam_in[r * 3 + tid] : ray_in[r * 3 + tid - 3];
    const float smin = g_smin[r];
    const float dz = g_smax[r] - smin;
    __syncthreads();

    if (tid < SAMP_P) {
        int i = round * SAMP_P + tid;
        float z = fmaf(dz, (float)i * INV99, smin);
        pts[tid * 3 + 0] = fmaf(z, s_cr[3], s_cr[0]);
        pts[tid * 3 + 1] = fmaf(z, s_cr[4], s_cr[1]);
        pts[tid * 3 + 2] = fmaf(z, s_cr[5], s_cr[2]);
    }
    __syncthreads();
    sdf_eval<SAMP_P>(W1, b1, W2, b2, W3, b3v, pts, h1s, red, sdfv);
    if (tid < SAMP_P) g_sdf[r * 100 + round * SAMP_P + tid] = sdfv[tid];
}

// ---------------- kernel 3: per-ray argmin + bracket / output ----------------
// 128 threads = 4 warps; warp w handles masked ray index blockIdx.x*4+w
__global__ __launch_bounds__(128, 8)
void argmin_kernel(
    const float* __restrict__ cam_in, const float* __restrict__ ray_in,
    float* __restrict__ out, int R)
{
    const int lane = threadIdx.x & 31;
    const int li = blockIdx.x * 4 + (threadIdx.x >> 5);
    if (li >= g_nmasked) return;
    const int r = g_mlist[li];
    const float* s100 = g_sdf + r * 100;

    // lexicographic min of (sign(s)*(100-i), i)
    float bt = 3.0e38f; int bi = 0;
    for (int i = lane; i < 100; i += 32) {
        float s = s100[i];
        float sg = (s > 0.f) ? 1.f : ((s < 0.f) ? -1.f : 0.f);
        float t = sg * (float)(100 - i);
        if (t < bt) { bt = t; bi = i; }   // i increasing -> first occurrence kept
    }
#pragma unroll
    for (int off = 16; off; off >>= 1) {
        float t2 = __shfl_down_sync(0xffffffffu, bt, off);
        int   i2 = __shfl_down_sync(0xffffffffu, bi, off);
        if (t2 < bt || (t2 == bt && i2 < bi)) { bt = t2; bi = i2; }
    }
    if (lane == 0) {
        const float smin = g_smin[r];
        const float dz = g_smax[r] - smin;
        int ind = bi;
        int il = (ind + 99) % 100;       // torch's (ind-1) wrap
        float zlo = fmaf(dz, (float)il  * INV99, smin);
        float zhi = fmaf(dz, (float)ind * INV99, smin);
        float slo = s100[il], shi = s100[ind];
        if (shi < 0.f) {
            float den = shi - slo; if (fabsf(den) <= 1e-12f) den = 1e-12f;
            float zp = -slo * (zhi - zlo) / den + zlo;
            g_zlo[r] = zlo; g_zhi[r] = zhi; g_slo[r] = slo; g_shi[r] = shi; g_zp[r] = zp;
            int pos = atomicAdd(&g_seccount, 1);
            g_seclist[pos] = r;
        } else {
            float dist = zhi;            // s_dists = z_vals[ind]
            float cx = cam_in[r*3+0], cy = cam_in[r*3+1], cz = cam_in[r*3+2];
            float rx = ray_in[r*3+0], ry = ray_in[r*3+1], rz = ray_in[r*3+2];
            out[r * 3 + 0] = fmaf(dist, rx, cx);
            out[r * 3 + 1] = fmaf(dist, ry, cy);
            out[r * 3 + 2] = fmaf(dist, rz, cz);
            out[R * 3 + r] = 0.f;        // net_surface false
            out[R * 4 + r] = dist;
        }
    }
}

// ---------------- kernel 4: batched secant (net_surface rays) ----------------
__global__ __launch_bounds__(256, 4)
void secant_kernel(
    const float* __restrict__ cam_in, const float* __restrict__ ray_in,
    const float* __restrict__ W1, const float* __restrict__ b1,
    const float* __restrict__ W2, const float* __restrict__ b2,
    const float* __restrict__ W3, const float* __restrict__ b3,
    float* __restrict__ out, int R)
{
    const int base = blockIdx.x * SEC_G;
    if (base >= g_seccount) return;   // uniform exit before any sync

    __shared__ float h1s[256 * SEC_G];
    __shared__ float red[8 * SEC_G];
    __shared__ float pts[SEC_G * 3];
    __shared__ float sdfv[SEC_G];
    __shared__ float s_cr[SEC_G][6];
    __shared__ float s_zlo[SEC_G], s_zhi[SEC_G], s_slo[SEC_G], s_shi[SEC_G], s_zp[SEC_G];
    __shared__ int   s_r[SEC_G];
    __shared__ int   s_n;

    const int tid = threadIdx.x;
    const float b3v = b3[0];
    if (tid == 0) {
        int c = g_seccount - base;
        s_n = (c < SEC_G) ? c : SEC_G;
    }
    __syncthreads();
    const int n = s_n;
    if (tid < SEC_G) {
        int li = (tid < n) ? tid : 0;
        int r = g_seclist[base + li];
        s_r[tid] = (tid < n) ? r : -1;
        s_zlo[tid] = g_zlo[r]; s_zhi[tid] = g_zhi[r];
        s_slo[tid] = g_slo[r]; s_shi[tid] = g_shi[r];
        s_zp[tid]  = g_zp[r];
        s_cr[tid][0] = cam_in[r*3+0]; s_cr[tid][1] = cam_in[r*3+1]; s_cr[tid][2] = cam_in[r*3+2];
        s_cr[tid][3] = ray_in[r*3+0]; s_cr[tid][4] = ray_in[r*3+1]; s_cr[tid][5] = ray_in[r*3+2];
    }
    __syncthreads();

    for (int it = 0; it < 8; ++it) {
        if (tid < SEC_G) {
            float zp = s_zp[tid];
            pts[tid * 3 + 0] = fmaf(zp, s_cr[tid][3], s_cr[tid][0]);
            pts[tid * 3 + 1] = fmaf(zp, s_cr[tid][4], s_cr[tid][1]);
            pts[tid * 3 + 2] = fmaf(zp, s_cr[tid][5], s_cr[tid][2]);
        }
        __syncthreads();
        sdf_eval<SEC_G>(W1, b1, W2, b2, W3, b3v, pts, h1s, red, sdfv);
        if (tid < SEC_G) {
            float mid = sdfv[tid];
            if (mid > 0.f) { s_zlo[tid] = s_zp[tid]; s_slo[tid] = mid; }
            if (mid < 0.f) { s_zhi[tid] = s_zp[tid]; s_shi[tid] = mid; }
            float den = s_shi[tid] - s_slo[tid];
            if (fabsf(den) <= 1e-12f) den = 1e-12f;
            s_zp[tid] = -s_slo[tid] * (s_zhi[tid] - s_zlo[tid]) / den + s_zlo[tid];
        }
        __syncthreads();
    }

    if (tid < n) {
        int r = s_r[tid];
        float dist = s_zp[tid];
        out[r * 3 + 0] = fmaf(dist, s_cr[tid][3], s_cr[tid][0]);
        out[r * 3 + 1] = fmaf(dist, s_cr[tid][4], s_cr[tid][1]);
        out[r * 3 + 2] = fmaf(dist, s_cr[tid][5], s_cr[tid][2]);
        out[R * 3 + r] = 1.f;          // net_surface true
        out[R * 4 + r] = dist;
    }
}

// ---------------- launch ----------------
extern "C" void kernel_launch(void* const* d_in, const int* in_sizes, int n_in,
                              void* d_out, int out_size)
{
    const float* cam  = (const float*)d_in[0];
    const float* rays = (const float*)d_in[1];
    // d_in[2] = object_mask (unused by the eval-mode forward)
    const float* W1 = (const float*)d_in[3];
    const float* b1 = (const float*)d_in[4];
    const float* W2 = (const float*)d_in[5];
    const float* b2 = (const float*)d_in[6];
    const float* W3 = (const float*)d_in[7];
    const float* b3 = (const float*)d_in[8];
    int R = in_sizes[0] / 3;
    if (R > RMAX) R = RMAX;
    float* out = (float*)d_out;

    init_kernel<<<1, 1>>>();
    trace_kernel<<<(R + TRACE_G - 1) / TRACE_G, 256>>>(cam, rays, W1, b1, W2, b2, W3, b3, out, R);
    samp_eval_kernel<<<R * 5, 256>>>(cam, rays, W1, b1, W2, b2, W3, b3);
    argmin_kernel<<<(R + 3) / 4, 128>>>(cam, rays, out, R);
    secant_kernel<<<(R + SEC_G - 1) / SEC_G, 256>>>(cam, rays, W1, b1, W2, b2, W3, b3, out, R);
}

// round 4
// speedup vs baseline: 1.3620x; 1.0453x over previous
#include <cuda_runtime.h>
#include <math.h>

// ---------------- constants ----------------
#define RMAX 8192
static constexpr float SDF_T = 5e-05f;
static constexpr int   TRACE_G = 8;    // rays per trace block
static constexpr int   TRACE_P = 16;   // points per eval round (2*G)
static constexpr int   SAMP_P  = 20;   // points per sampler block
static constexpr int   SEC_G   = 8;    // rays per secant block
static constexpr float INV99   = 1.0f / 99.0f;

// inter-kernel scratch (no allocations allowed)
__device__ float g_smin[RMAX];
__device__ float g_smax[RMAX];
__device__ int   g_mlist[RMAX];
__device__ int   g_nmasked;
__device__ int   g_seclist[RMAX];
__device__ int   g_seccount;
__device__ float g_zlo[RMAX], g_zhi[RMAX], g_slo[RMAX], g_shi[RMAX], g_zp[RMAX];
__device__ float g_sdf[RMAX * 100];

__global__ void init_kernel() { g_nmasked = 0; g_seccount = 0; }

// ---------------- f32x2 helpers (FFMA2 — ptxas won't auto-fuse) ----------------
__device__ __forceinline__ unsigned long long pack2(float a, float b) {
    unsigned long long r;
    asm("mov.b64 %0, {%1, %2};" : "=l"(r) : "f"(a), "f"(b));
    return r;
}
__device__ __forceinline__ void unpack2(unsigned long long v, float& a, float& b) {
    asm("mov.b64 {%0, %1}, %2;" : "=f"(a), "=f"(b) : "l"(v));
}
__device__ __forceinline__ unsigned long long fma2(unsigned long long a,
                                                   unsigned long long b,
                                                   unsigned long long c) {
    unsigned long long d;
    asm("fma.rn.f32x2 %0, %1, %2, %3;" : "=l"(d) : "l"(a), "l"(b), "l"(c));
    return d;
}

// ---------------- batched SDF eval ----------------
// Evaluates sdf(p) for P points (P % 4 == 0). All 256 threads participate.
// Layer 2 uses packed f32x2 FMA (two points per instruction) + depth-2
// software pipeline on W2 global loads.
template<int P>
__device__ __forceinline__ void sdf_eval(
    const float* __restrict__ W1, const float* __restrict__ b1,
    const float* __restrict__ W2, const float* __restrict__ b2,
    const float* __restrict__ W3, float b3v,
    const float* pts, float* h1s, float* red, float* sdfv)
{
    const int tid = threadIdx.x;

    // ---- layer 1: h1[k][p] = tanh(p . W1[:,k] + b1[k]) ----
#pragma unroll
    for (int it = 0; it < P; ++it) {
        int idx = it * 256 + tid;       // coalesced writes
        int k = idx / P;
        int p = idx - k * P;
        float x = pts[p * 3 + 0], y = pts[p * 3 + 1], z = pts[p * 3 + 2];
        float v = fmaf(W1[k], x, fmaf(W1[256 + k], y, fmaf(W1[512 + k], z, b1[k])));
        h1s[idx] = tanhf(v);
    }
    __syncthreads();

    // ---- layer 2: thread j owns neuron j; f32x2 packed accumulate ----
    constexpr int P2 = P / 2;
    constexpr int P4 = P / 4;
    unsigned long long acc2[P2];
#pragma unroll
    for (int q = 0; q < P2; ++q) acc2[q] = 0ull;   // (0.f,0.f)

    const float* W2j = W2 + tid;
    float w0[8], w1[8];
#pragma unroll
    for (int u = 0; u < 8; ++u) w0[u] = W2j[u * 256];
#pragma unroll
    for (int u = 0; u < 8; ++u) w1[u] = W2j[(8 + u) * 256];

#pragma unroll 1
    for (int k0 = 0; k0 < 256; k0 += 8) {
        float wn[8];
        int kp = k0 + 16;
        if (kp < 256) {
#pragma unroll
            for (int u = 0; u < 8; ++u) wn[u] = W2j[(kp + u) * 256];
        } else {
#pragma unroll
            for (int u = 0; u < 8; ++u) wn[u] = 0.f;
        }
#pragma unroll
        for (int u = 0; u < 8; ++u) {
            unsigned long long ww = pack2(w0[u], w0[u]);
            const ulonglong2* h2 = reinterpret_cast<const ulonglong2*>(h1s + (k0 + u) * P);
#pragma unroll
            for (int q = 0; q < P4; ++q) {
                ulonglong2 v = h2[q];                 // broadcast LDS.128 = 2x f32x2
                acc2[q * 2 + 0] = fma2(v.x, ww, acc2[q * 2 + 0]);
                acc2[q * 2 + 1] = fma2(v.y, ww, acc2[q * 2 + 1]);
            }
        }
#pragma unroll
        for (int u = 0; u < 8; ++u) { w0[u] = w1[u]; w1[u] = wn[u]; }
    }

    // ---- layer 3 ----
    const float bb2 = b2[tid];
    const float w3j = W3[tid];
#pragma unroll
    for (int q = 0; q < P2; ++q) {
        float a0, a1;
        unpack2(acc2[q], a0, a1);
        float av[2] = {a0, a1};
#pragma unroll
        for (int c = 0; c < 2; ++c) {
            int p = q * 2 + c;
            float m = tanhf(av[c] + bb2) * w3j;
#pragma unroll
            for (int off = 16; off; off >>= 1)
                m += __shfl_down_sync(0xffffffffu, m, off);
            if ((tid & 31) == 0) red[p * 8 + (tid >> 5)] = m;
        }
    }
    __syncthreads();
    if (tid < P) {
        float s = 0.f;
#pragma unroll
        for (int q = 0; q < 8; ++q) s += red[tid * 8 + q];
        float x = pts[tid * 3 + 0], y = pts[tid * 3 + 1], z = pts[tid * 3 + 2];
        float base = sqrtf(fmaf(x, x, fmaf(y, y, fmaf(z, z, 1e-12f)))) - 0.6f;
        sdfv[tid] = base + 0.05f * (s + b3v);
    }
    __syncthreads();
}

// ---------------- kernel 1: init + sphere tracing ----------------
__global__ __launch_bounds__(256, 4)
void trace_kernel(
    const float* __restrict__ cam_in, const float* __restrict__ ray_in,
    const float* __restrict__ W1, const float* __restrict__ b1,
    const float* __restrict__ W2, const float* __restrict__ b2,
    const float* __restrict__ W3, const float* __restrict__ b3,
    float* __restrict__ out, int R)
{
    __shared__ __align__(16) float h1s[256 * TRACE_P];
    __shared__ float red[8 * TRACE_P];
    __shared__ float pts[TRACE_P * 3];
    __shared__ float sdfv[TRACE_P];
    __shared__ float s_cam[TRACE_G][3], s_ray[TRACE_G][3];
    __shared__ float s_acc_s[TRACE_G], s_acc_e[TRACE_G];
    __shared__ float s_nsdf_s[TRACE_G], s_nsdf_e[TRACE_G];
    __shared__ float s_csdf_s[TRACE_G], s_csdf_e[TRACE_G];
    __shared__ int   s_unfin_s[TRACE_G], s_unfin_e[TRACE_G];
    __shared__ int   s_np_s[TRACE_G], s_np_e[TRACE_G];
    __shared__ int   s_flag;

    const int tid   = threadIdx.x;
    const int rbase = blockIdx.x * TRACE_G;
    const float b3v = b3[0];

    if (tid < TRACE_G) {
        int r = rbase + tid;
        float cx = 0.f, cy = 0.f, cz = 0.f, rx = 0.f, ry = 0.f, rz = 0.f;
        bool valid = (r < R);
        if (valid) {
            cx = cam_in[r * 3 + 0]; cy = cam_in[r * 3 + 1]; cz = cam_in[r * 3 + 2];
            rx = ray_in[r * 3 + 0]; ry = ray_in[r * 3 + 1]; rz = ray_in[r * 3 + 2];
        }
        s_cam[tid][0] = cx; s_cam[tid][1] = cy; s_cam[tid][2] = cz;
        s_ray[tid][0] = rx; s_ray[tid][1] = ry; s_ray[tid][2] = rz;
        float dt = rx * cx + ry * cy + rz * cz;
        float cc = cx * cx + cy * cy + cz * cz;
        float under = dt * dt - (cc - 1.0f);
        bool mi = valid && (under > 0.f);
        float sq = sqrtf(mi ? under : 1.0f);
        float i0 = mi ? fmaxf(-sq - dt, 0.f) : 0.f;
        float i1 = mi ? fmaxf( sq - dt, 0.f) : 0.f;
        s_acc_s[tid] = i0; s_acc_e[tid] = i1;
        s_unfin_s[tid] = mi ? 1 : 0;
        s_unfin_e[tid] = mi ? 1 : 0;
    }
    __syncthreads();

    if (tid < TRACE_P) {
        int g = tid >> 1;
        float a = (tid & 1) ? s_acc_e[g] : s_acc_s[g];
        pts[tid * 3 + 0] = fmaf(a, s_ray[g][0], s_cam[g][0]);
        pts[tid * 3 + 1] = fmaf(a, s_ray[g][1], s_cam[g][1]);
        pts[tid * 3 + 2] = fmaf(a, s_ray[g][2], s_cam[g][2]);
    }
    __syncthreads();
    sdf_eval<TRACE_P>(W1, b1, W2, b2, W3, b3v, pts, h1s, red, sdfv);
    if (tid < TRACE_G) {
        s_nsdf_s[tid] = s_unfin_s[tid] ? sdfv[tid * 2 + 0] : 0.f;
        s_nsdf_e[tid] = s_unfin_e[tid] ? sdfv[tid * 2 + 1] : 0.f;
    }
    __syncthreads();

    for (int iter = 0; iter < 10; ++iter) {
        if (tid == 0) s_flag = 0;
        __syncthreads();
        if (tid < TRACE_G) {
            float cs = s_unfin_s[tid] ? s_nsdf_s[tid] : 0.f;
            cs = (cs <= SDF_T) ? 0.f : cs;
            float ce = s_unfin_e[tid] ? s_nsdf_e[tid] : 0.f;
            ce = (ce <= SDF_T) ? 0.f : ce;
            int us = s_unfin_s[tid] & (cs > SDF_T);
            int ue = s_unfin_e[tid] & (ce > SDF_T);
            s_unfin_s[tid] = us; s_unfin_e[tid] = ue;
            s_csdf_s[tid] = cs; s_csdf_e[tid] = ce;
            s_acc_s[tid] += cs;
            s_acc_e[tid] -= ce;
            if (us | ue) s_flag = 1;   // benign race, all write 1
        }
        __syncthreads();
        if (!s_flag) break;            // exact: state invariant once all finished

        if (tid < TRACE_P) {
            int g = tid >> 1;
            float a = (tid & 1) ? s_acc_e[g] : s_acc_s[g];
            pts[tid * 3 + 0] = fmaf(a, s_ray[g][0], s_cam[g][0]);
            pts[tid * 3 + 1] = fmaf(a, s_ray[g][1], s_cam[g][1]);
            pts[tid * 3 + 2] = fmaf(a, s_ray[g][2], s_cam[g][2]);
        }
        __syncthreads();
        sdf_eval<TRACE_P>(W1, b1, W2, b2, W3, b3v, pts, h1s, red, sdfv);
        if (tid == 0) s_flag = 0;
        __syncthreads();
        if (tid < TRACE_G) {
            float ns = s_unfin_s[tid] ? sdfv[tid * 2 + 0] : 0.f;
            float ne = s_unfin_e[tid] ? sdfv[tid * 2 + 1] : 0.f;
            int nps = (ns < 0.f) ? 1 : 0;
            int npe = (ne < 0.f) ? 1 : 0;
            s_nsdf_s[tid] = ns; s_nsdf_e[tid] = ne;
            s_np_s[tid] = nps; s_np_e[tid] = npe;
            if (nps) s_acc_s[tid] -= 0.5f * s_csdf_s[tid];
            if (npe) s_acc_e[tid] += 0.5f * s_csdf_e[tid];
            if (nps | npe) s_flag = 1;
        }
        __syncthreads();
        if (s_flag) {
            if (tid < TRACE_P) {
                int g = tid >> 1;
                float a = (tid & 1) ? s_acc_e[g] : s_acc_s[g];
                pts[tid * 3 + 0] = fmaf(a, s_ray[g][0], s_cam[g][0]);
                pts[tid * 3 + 1] = fmaf(a, s_ray[g][1], s_cam[g][1]);
                pts[tid * 3 + 2] = fmaf(a, s_ray[g][2], s_cam[g][2]);
            }
            __syncthreads();
            sdf_eval<TRACE_P>(W1, b1, W2, b2, W3, b3v, pts, h1s, red, sdfv);
            if (tid < TRACE_G) {
                if (s_np_s[tid]) s_nsdf_s[tid] = sdfv[tid * 2 + 0];
                if (s_np_e[tid]) s_nsdf_e[tid] = sdfv[tid * 2 + 1];
            }
            __syncthreads();
        }
        if (tid < TRACE_G) {
            int lt = (s_acc_s[tid] < s_acc_e[tid]) ? 1 : 0;
            s_unfin_s[tid] &= lt;
            s_unfin_e[tid] &= lt;
        }
        __syncthreads();
    }

    if (tid < TRACE_G) {
        int r = rbase + tid;
        if (r < R) {
            float cs = s_unfin_s[tid] ? s_nsdf_s[tid] : 0.f;
            cs = (cs <= SDF_T) ? 0.f : cs;
            int mask = s_unfin_s[tid] & ((cs > SDF_T) ? 1 : 0);
            g_smin[r] = s_acc_s[tid];
            g_smax[r] = s_acc_e[tid];
            if (mask) {
                int pos = atomicAdd(&g_nmasked, 1);
                g_mlist[pos] = r;
            }
            float as = s_acc_s[tid];
            out[r * 3 + 0] = fmaf(as, s_ray[tid][0], s_cam[tid][0]);
            out[r * 3 + 1] = fmaf(as, s_ray[tid][1], s_cam[tid][1]);
            out[r * 3 + 2] = fmaf(as, s_ray[tid][2], s_cam[tid][2]);
            out[R * 3 + r] = (as < s_acc_e[tid]) ? 1.f : 0.f;
            out[R * 4 + r] = as;
        }
    }
}

// ---------------- kernel 2: fully-parallel uniform sampler ----------------
__global__ __launch_bounds__(256, 4)
void samp_eval_kernel(
    const float* __restrict__ cam_in, const float* __restrict__ ray_in,
    const float* __restrict__ W1, const float* __restrict__ b1,
    const float* __restrict__ W2, const float* __restrict__ b2,
    const float* __restrict__ W3, const float* __restrict__ b3)
{
    const int li = blockIdx.x / 5;
    if (li >= g_nmasked) return;      // uniform early-exit, before any sync
    const int round = blockIdx.x - li * 5;
    const int r = g_mlist[li];

    __shared__ __align__(16) float h1s[256 * SAMP_P];
    __shared__ float red[8 * SAMP_P];
    __shared__ float pts[SAMP_P * 3];
    __shared__ float sdfv[SAMP_P];
    __shared__ float s_cr[6];

    const int tid = threadIdx.x;
    const float b3v = b3[0];
    if (tid < 6)
        s_cr[tid] = (tid < 3) ? cam_in[r * 3 + tid] : ray_in[r * 3 + tid - 3];
    const float smin = g_smin[r];
    const float dz = g_smax[r] - smin;
    __syncthreads();

    if (tid < SAMP_P) {
        int i = round * SAMP_P + tid;
        float z = fmaf(dz, (float)i * INV99, smin);
        pts[tid * 3 + 0] = fmaf(z, s_cr[3], s_cr[0]);
        pts[tid * 3 + 1] = fmaf(z, s_cr[4], s_cr[1]);
        pts[tid * 3 + 2] = fmaf(z, s_cr[5], s_cr[2]);
    }
    __syncthreads();
    sdf_eval<SAMP_P>(W1, b1, W2, b2, W3, b3v, pts, h1s, red, sdfv);
    if (tid < SAMP_P) g_sdf[r * 100 + round * SAMP_P + tid] = sdfv[tid];
}

// ---------------- kernel 3: per-ray argmin + bracket / output ----------------
__global__ __launch_bounds__(128, 8)
void argmin_kernel(
    const float* __restrict__ cam_in, const float* __restrict__ ray_in,
    float* __restrict__ out, int R)
{
    const int lane = threadIdx.x & 31;
    const int li = blockIdx.x * 4 + (threadIdx.x >> 5);
    if (li >= g_nmasked) return;
    const int r = g_mlist[li];
    const float* s100 = g_sdf + r * 100;

    float bt = 3.0e38f; int bi = 0;
    for (int i = lane; i < 100; i += 32) {
        float s = s100[i];
        float sg = (s > 0.f) ? 1.f : ((s < 0.f) ? -1.f : 0.f);
        float t = sg * (float)(100 - i);
        if (t < bt) { bt = t; bi = i; }
    }
#pragma unroll
    for (int off = 16; off; off >>= 1) {
        float t2 = __shfl_down_sync(0xffffffffu, bt, off);
        int   i2 = __shfl_down_sync(0xffffffffu, bi, off);
        if (t2 < bt || (t2 == bt && i2 < bi)) { bt = t2; bi = i2; }
    }
    if (lane == 0) {
        const float smin = g_smin[r];
        const float dz = g_smax[r] - smin;
        int ind = bi;
        int il = (ind + 99) % 100;       // torch's (ind-1) wrap
        float zlo = fmaf(dz, (float)il  * INV99, smin);
        float zhi = fmaf(dz, (float)ind * INV99, smin);
        float slo = s100[il], shi = s100[ind];
        if (shi < 0.f) {
            float den = shi - slo; if (fabsf(den) <= 1e-12f) den = 1e-12f;
            float zp = -slo * (zhi - zlo) / den + zlo;
            g_zlo[r] = zlo; g_zhi[r] = zhi; g_slo[r] = slo; g_shi[r] = shi; g_zp[r] = zp;
            int pos = atomicAdd(&g_seccount, 1);
            g_seclist[pos] = r;
        } else {
            float dist = zhi;            // s_dists = z_vals[ind]
            float cx = cam_in[r*3+0], cy = cam_in[r*3+1], cz = cam_in[r*3+2];
            float rx = ray_in[r*3+0], ry = ray_in[r*3+1], rz = ray_in[r*3+2];
            out[r * 3 + 0] = fmaf(dist, rx, cx);
            out[r * 3 + 1] = fmaf(dist, ry, cy);
            out[r * 3 + 2] = fmaf(dist, rz, cz);
            out[R * 3 + r] = 0.f;        // net_surface false
            out[R * 4 + r] = dist;
        }
    }
}

// ---------------- kernel 4: batched secant (net_surface rays) ----------------
__global__ __launch_bounds__(256, 4)
void secant_kernel(
    const float* __restrict__ cam_in, const float* __restrict__ ray_in,
    const float* __restrict__ W1, const float* __restrict__ b1,
    const float* __restrict__ W2, const float* __restrict__ b2,
    const float* __restrict__ W3, const float* __restrict__ b3,
    float* __restrict__ out, int R)
{
    const int base = blockIdx.x * SEC_G;
    if (base >= g_seccount) return;   // uniform exit before any sync

    __shared__ __align__(16) float h1s[256 * SEC_G];
    __shared__ float red[8 * SEC_G];
    __shared__ float pts[SEC_G * 3];
    __shared__ float sdfv[SEC_G];
    __shared__ float s_cr[SEC_G][6];
    __shared__ float s_zlo[SEC_G], s_zhi[SEC_G], s_slo[SEC_G], s_shi[SEC_G], s_zp[SEC_G];
    __shared__ int   s_r[SEC_G];
    __shared__ int   s_n;

    const int tid = threadIdx.x;
    const float b3v = b3[0];
    if (tid == 0) {
        int c = g_seccount - base;
        s_n = (c < SEC_G) ? c : SEC_G;
    }
    __syncthreads();
    const int n = s_n;
    if (tid < SEC_G) {
        int li = (tid < n) ? tid : 0;
        int r = g_seclist[base + li];
        s_r[tid] = (tid < n) ? r : -1;
        s_zlo[tid] = g_zlo[r]; s_zhi[tid] = g_zhi[r];
        s_slo[tid] = g_slo[r]; s_shi[tid] = g_shi[r];
        s_zp[tid]  = g_zp[r];
        s_cr[tid][0] = cam_in[r*3+0]; s_cr[tid][1] = cam_in[r*3+1]; s_cr[tid][2] = cam_in[r*3+2];
        s_cr[tid][3] = ray_in[r*3+0]; s_cr[tid][4] = ray_in[r*3+1]; s_cr[tid][5] = ray_in[r*3+2];
    }
    __syncthreads();

    for (int it = 0; it < 8; ++it) {
        if (tid < SEC_G) {
            float zp = s_zp[tid];
            pts[tid * 3 + 0] = fmaf(zp, s_cr[tid][3], s_cr[tid][0]);
            pts[tid * 3 + 1] = fmaf(zp, s_cr[tid][4], s_cr[tid][1]);
            pts[tid * 3 + 2] = fmaf(zp, s_cr[tid][5], s_cr[tid][2]);
        }
        __syncthreads();
        sdf_eval<SEC_G>(W1, b1, W2, b2, W3, b3v, pts, h1s, red, sdfv);
        if (tid < SEC_G) {
            float mid = sdfv[tid];
            if (mid > 0.f) { s_zlo[tid] = s_zp[tid]; s_slo[tid] = mid; }
            if (mid < 0.f) { s_zhi[tid] = s_zp[tid]; s_shi[tid] = mid; }
            float den = s_shi[tid] - s_slo[tid];
            if (fabsf(den) <= 1e-12f) den = 1e-12f;
            s_zp[tid] = -s_slo[tid] * (s_zhi[tid] - s_zlo[tid]) / den + s_zlo[tid];
        }
        __syncthreads();
    }

    if (tid < n) {
        int r = s_r[tid];
        float dist = s_zp[tid];
        out[r * 3 + 0] = fmaf(dist, s_cr[tid][3], s_cr[tid][0]);
        out[r * 3 + 1] = fmaf(dist, s_cr[tid][4], s_cr[tid][1]);
        out[r * 3 + 2] = fmaf(dist, s_cr[tid][5], s_cr[tid][2]);
        out[R * 3 + r] = 1.f;          // net_surface true
        out[R * 4 + r] = dist;
    }
}

// ---------------- launch ----------------
extern "C" void kernel_launch(void* const* d_in, const int* in_sizes, int n_in,
                              void* d_out, int out_size)
{
    const float* cam  = (const float*)d_in[0];
    const float* rays = (const float*)d_in[1];
    // d_in[2] = object_mask (unused by the eval-mode forward)
    const float* W1 = (const float*)d_in[3];
    const float* b1 = (const float*)d_in[4];
    const float* W2 = (const float*)d_in[5];
    const float* b2 = (const float*)d_in[6];
    const float* W3 = (const float*)d_in[7];
    const float* b3 = (const float*)d_in[8];
    int R = in_sizes[0] / 3;
    if (R > RMAX) R = RMAX;
    float* out = (float*)d_out;

    init_kernel<<<1, 1>>>();
    trace_kernel<<<(R + TRACE_G - 1) / TRACE_G, 256>>>(cam, rays, W1, b1, W2, b2, W3, b3, out, R);
    samp_eval_kernel<<<R * 5, 256>>>(cam, rays, W1, b1, W2, b2, W3, b3);
    argmin_kernel<<<(R + 3) / 4, 128>>>(cam, rays, out, R);
    secant_kernel<<<(R + SEC_G - 1) / SEC_G, 256>>>(cam, rays, W1, b1, W2, b2, W3, b3, out, R);
}

// round 5
// speedup vs baseline: 1.3839x; 1.0161x over previous
#include <cuda_runtime.h>
#include <math.h>

// ---------------- constants ----------------
#define RMAX 8192
static constexpr float SDF_T = 5e-05f;
static constexpr float INV99 = 1.0f / 99.0f;

// ---------------- inter-kernel scratch ----------------
__device__ float g_acc_s[RMAX], g_acc_e[RMAX];
__device__ float g_nsdf_s[RMAX], g_nsdf_e[RMAX];
__device__ float g_csdf_s[RMAX], g_csdf_e[RMAX];
__device__ int   g_unfin_s[RMAX], g_unfin_e[RMAX];
__device__ float g_smin[RMAX], g_smax[RMAX];
__device__ int   g_mlist[RMAX];
__device__ int   g_nmasked;
__device__ int   g_seclist[RMAX];
__device__ int   g_seccount;
__device__ float g_zlo[RMAX], g_zhi[RMAX], g_slo[RMAX], g_shi[RMAX], g_zp[RMAX];
__device__ float g_sdf[RMAX * 100];
__device__ int   g_elist[2 * RMAX];
__device__ int   g_ecnt[32];

__global__ void init_kernel() {
    int t = threadIdx.x;
    if (t < 32) g_ecnt[t] = 0;
    if (t == 32) g_nmasked = 0;
    if (t == 33) g_seccount = 0;
}

// ---------------- f32x2 helpers ----------------
__device__ __forceinline__ unsigned long long pack2(float a, float b) {
    unsigned long long r;
    asm("mov.b64 %0, {%1, %2};" : "=l"(r) : "f"(a), "f"(b));
    return r;
}
__device__ __forceinline__ void unpack2(unsigned long long v, float& a, float& b) {
    asm("mov.b64 {%0, %1}, %2;" : "=f"(a), "=f"(b) : "l"(v));
}
__device__ __forceinline__ unsigned long long fma2(unsigned long long a,
                                                   unsigned long long b,
                                                   unsigned long long c) {
    unsigned long long d;
    asm("fma.rn.f32x2 %0, %1, %2, %3;" : "=l"(d) : "l"(a), "l"(b), "l"(c));
    return d;
}

__device__ __forceinline__ float tanh_fast(float x) {
    x = fminf(fmaxf(x, -15.f), 15.f);
    float e = __expf(2.f * x);
    return (e - 1.f) * __fdividef(1.f, e + 1.f);
}

// ---------------- batched SDF eval, P = 32 points, 256 threads ----------------
// layer2 tiling: thread = (neuron pair npair = tid&127) x (point half = tid>>7).
// Each h LDS.128 feeds 2 neurons -> 4 FFMA2 per LDS (LDS no longer co-limits).
__device__ __forceinline__ void sdf_eval32(
    const float* __restrict__ W1, const float* __restrict__ b1,
    const float* __restrict__ W2, const float* __restrict__ b2,
    const float* __restrict__ W3, float b3v,
    const float* pts, float* h1s, float* red, float* sdfv)
{
    const int tid = threadIdx.x;

    // ---- layer 1: h1[k*32+p] = tanh(p . W1[:,k] + b1[k]) ----
#pragma unroll
    for (int it = 0; it < 32; ++it) {
        int idx = it * 256 + tid;      // coalesced; warp-uniform k
        int k = idx >> 5;
        int p = idx & 31;
        float x = pts[p * 3 + 0], y = pts[p * 3 + 1], z = pts[p * 3 + 2];
        float v = fmaf(W1[k], x, fmaf(W1[256 + k], y, fmaf(W1[512 + k], z, b1[k])));
        h1s[idx] = tanh_fast(v);
    }
    __syncthreads();

    // ---- layer 2 ----
    const int half  = tid >> 7;        // 0: points 0-15, 1: points 16-31
    const int npair = tid & 127;       // neurons 2*npair, 2*npair+1
    unsigned long long accA[8], accB[8];
#pragma unroll
    for (int q = 0; q < 8; ++q) { accA[q] = 0ull; accB[q] = 0ull; }

    const float2* W2p = reinterpret_cast<const float2*>(W2) + npair;
    const float* hbase = h1s + half * 16;

    float2 w0[2], w1[2];
#pragma unroll
    for (int u = 0; u < 2; ++u) w0[u] = W2p[u * 128];
#pragma unroll
    for (int u = 0; u < 2; ++u) w1[u] = W2p[(2 + u) * 128];

#pragma unroll 1
    for (int k0 = 0; k0 < 256; k0 += 2) {
        float2 wn[2];
        int kp = k0 + 4;
        if (kp < 256) {
#pragma unroll
            for (int u = 0; u < 2; ++u) wn[u] = W2p[(kp + u) * 128];
        } else {
#pragma unroll
            for (int u = 0; u < 2; ++u) wn[u] = make_float2(0.f, 0.f);
        }
#pragma unroll
        for (int u = 0; u < 2; ++u) {
            unsigned long long wA = pack2(w0[u].x, w0[u].x);
            unsigned long long wB = pack2(w0[u].y, w0[u].y);
            const ulonglong2* h2 =
                reinterpret_cast<const ulonglong2*>(hbase + (k0 + u) * 32);
            ulonglong2 v0 = h2[0], v1 = h2[1], v2 = h2[2], v3 = h2[3];
            accA[0] = fma2(v0.x, wA, accA[0]); accB[0] = fma2(v0.x, wB, accB[0]);
            accA[1] = fma2(v0.y, wA, accA[1]); accB[1] = fma2(v0.y, wB, accB[1]);
            accA[2] = fma2(v1.x, wA, accA[2]); accB[2] = fma2(v1.x, wB, accB[2]);
            accA[3] = fma2(v1.y, wA, accA[3]); accB[3] = fma2(v1.y, wB, accB[3]);
            accA[4] = fma2(v2.x, wA, accA[4]); accB[4] = fma2(v2.x, wB, accB[4]);
            accA[5] = fma2(v2.y, wA, accA[5]); accB[5] = fma2(v2.y, wB, accB[5]);
            accA[6] = fma2(v3.x, wA, accA[6]); accB[6] = fma2(v3.x, wB, accB[6]);
            accA[7] = fma2(v3.y, wA, accA[7]); accB[7] = fma2(v3.y, wB, accB[7]);
        }
#pragma unroll
        for (int u = 0; u < 2; ++u) { w0[u] = w1[u]; w1[u] = wn[u]; }
    }

    // ---- layer 3 ----
    float2 b2v = reinterpret_cast<const float2*>(b2)[npair];
    float2 w3v = reinterpret_cast<const float2*>(W3)[npair];
    const int sub = (tid >> 5) & 3;    // warp index within half
#pragma unroll
    for (int q = 0; q < 8; ++q) {
        float a0, a1, c0, c1;
        unpack2(accA[q], a0, a1);
        unpack2(accB[q], c0, c1);
        float m0 = tanh_fast(a0 + b2v.x) * w3v.x + tanh_fast(c0 + b2v.y) * w3v.y;
        float m1 = tanh_fast(a1 + b2v.x) * w3v.x + tanh_fast(c1 + b2v.y) * w3v.y;
#pragma unroll
        for (int off = 16; off; off >>= 1) {
            m0 += __shfl_down_sync(0xffffffffu, m0, off);
            m1 += __shfl_down_sync(0xffffffffu, m1, off);
        }
        if ((tid & 31) == 0) {
            int p0 = half * 16 + 2 * q;
            red[p0 * 4 + sub] = m0;
            red[(p0 + 1) * 4 + sub] = m1;
        }
    }
    __syncthreads();
    if (tid < 32) {
        float s = red[tid * 4 + 0] + red[tid * 4 + 1] + red[tid * 4 + 2] + red[tid * 4 + 3];
        float x = pts[tid * 3 + 0], y = pts[tid * 3 + 1], z = pts[tid * 3 + 2];
        float base = sqrtf(fmaf(x, x, fmaf(y, y, fmaf(z, z, 1e-12f)))) - 0.6f;
        sdfv[tid] = base + 0.05f * (s + b3v);
    }
    __syncthreads();
}

// ---------------- trace step kernels ----------------
__global__ __launch_bounds__(256)
void k_tr_init(const float* __restrict__ cam_in, const float* __restrict__ ray_in, int R)
{
    int r = blockIdx.x * 256 + threadIdx.x;
    if (r >= R) return;
    float cx = cam_in[r*3+0], cy = cam_in[r*3+1], cz = cam_in[r*3+2];
    float rx = ray_in[r*3+0], ry = ray_in[r*3+1], rz = ray_in[r*3+2];
    float dt = rx*cx + ry*cy + rz*cz;
    float cc = cx*cx + cy*cy + cz*cz;
    float under = dt*dt - (cc - 1.0f);
    int mi = (under > 0.f) ? 1 : 0;
    float sq = sqrtf(mi ? under : 1.0f);
    float i0 = mi ? fmaxf(-sq - dt, 0.f) : 0.f;
    float i1 = mi ? fmaxf( sq - dt, 0.f) : 0.f;
    g_acc_s[r] = i0; g_acc_e[r] = i1;
    g_unfin_s[r] = mi; g_unfin_e[r] = mi;
    g_nsdf_s[r] = 0.f; g_nsdf_e[r] = 0.f;
    if (mi) {
        int pos = atomicAdd(&g_ecnt[0], 2);
        g_elist[pos]     = (r << 1);
        g_elist[pos + 1] = (r << 1) | 1;
    }
}

__global__ __launch_bounds__(256)
void k_step1(int R, int phase)
{
    int r = blockIdx.x * 256 + threadIdx.x;
    if (r >= R) return;
    int us0 = g_unfin_s[r];
    float cs = us0 ? g_nsdf_s[r] : 0.f;
    cs = (cs <= SDF_T) ? 0.f : cs;
    int us = us0 & ((cs > SDF_T) ? 1 : 0);
    g_csdf_s[r] = cs; g_unfin_s[r] = us;
    g_acc_s[r] += cs;

    int ue0 = g_unfin_e[r];
    float ce = ue0 ? g_nsdf_e[r] : 0.f;
    ce = (ce <= SDF_T) ? 0.f : ce;
    int ue = ue0 & ((ce > SDF_T) ? 1 : 0);
    g_csdf_e[r] = ce; g_unfin_e[r] = ue;
    g_acc_e[r] -= ce;

    if (!us) g_nsdf_s[r] = 0.f;
    if (!ue) g_nsdf_e[r] = 0.f;
    int n = us + ue;
    if (n) {
        int pos = atomicAdd(&g_ecnt[phase], n);
        if (us) g_elist[pos++] = (r << 1);
        if (ue) g_elist[pos]   = (r << 1) | 1;
    }
}

__global__ __launch_bounds__(256)
void k_step2(int R, int phase)
{
    int r = blockIdx.x * 256 + threadIdx.x;
    if (r >= R) return;
    int nps = (g_nsdf_s[r] < 0.f) ? 1 : 0;
    float as = g_acc_s[r];
    if (nps) { as -= 0.5f * g_csdf_s[r]; g_acc_s[r] = as; }
    int npe = (g_nsdf_e[r] < 0.f) ? 1 : 0;
    float ae = g_acc_e[r];
    if (npe) { ae += 0.5f * g_csdf_e[r]; g_acc_e[r] = ae; }
    int lt = (as < ae) ? 1 : 0;
    g_unfin_s[r] &= lt;
    g_unfin_e[r] &= lt;
    int n = nps + npe;
    if (n) {
        int pos = atomicAdd(&g_ecnt[phase], n);
        if (nps) g_elist[pos++] = (r << 1);
        if (npe) g_elist[pos]   = (r << 1) | 1;
    }
}

__global__ __launch_bounds__(256)
void k_final(const float* __restrict__ cam_in, const float* __restrict__ ray_in,
             float* __restrict__ out, int R)
{
    int r = blockIdx.x * 256 + threadIdx.x;
    if (r >= R) return;
    int us = g_unfin_s[r];
    float cs = us ? g_nsdf_s[r] : 0.f;
    cs = (cs <= SDF_T) ? 0.f : cs;
    int mask = us & ((cs > SDF_T) ? 1 : 0);
    float as = g_acc_s[r], ae = g_acc_e[r];
    g_smin[r] = as; g_smax[r] = ae;
    if (mask) {
        int pos = atomicAdd(&g_nmasked, 1);
        g_mlist[pos] = r;
    }
    float cx = cam_in[r*3+0], cy = cam_in[r*3+1], cz = cam_in[r*3+2];
    float rx = ray_in[r*3+0], ry = ray_in[r*3+1], rz = ray_in[r*3+2];
    out[r*3+0] = fmaf(as, rx, cx);
    out[r*3+1] = fmaf(as, ry, cy);
    out[r*3+2] = fmaf(as, rz, cz);
    out[R*3+r] = (as < ae) ? 1.f : 0.f;
    out[R*4+r] = as;
}

// ---------------- generic trace eval over compacted list ----------------
__global__ __launch_bounds__(256, 3)
void eval_trace(const float* __restrict__ cam_in, const float* __restrict__ ray_in,
                const float* __restrict__ W1, const float* __restrict__ b1,
                const float* __restrict__ W2, const float* __restrict__ b2,
                const float* __restrict__ W3, const float* __restrict__ b3,
                int phase)
{
    const int cnt = g_ecnt[phase];
    const int base = blockIdx.x * 32;
    if (base >= cnt) return;

    __shared__ __align__(16) float h1s[8192];
    __shared__ float red[128];
    __shared__ float pts[96];
    __shared__ float sdfv[32];
    __shared__ int   ent[32];

    const int tid = threadIdx.x;
    const float b3v = b3[0];
    if (tid < 32) {
        int i = base + tid;
        int e = g_elist[(i < cnt) ? i : (cnt - 1)];
        ent[tid] = e;
        int r = e >> 1;
        float a = (e & 1) ? g_acc_e[r] : g_acc_s[r];
        pts[tid*3+0] = fmaf(a, ray_in[r*3+0], cam_in[r*3+0]);
        pts[tid*3+1] = fmaf(a, ray_in[r*3+1], cam_in[r*3+1]);
        pts[tid*3+2] = fmaf(a, ray_in[r*3+2], cam_in[r*3+2]);
    }
    __syncthreads();
    sdf_eval32(W1, b1, W2, b2, W3, b3v, pts, h1s, red, sdfv);
    if (tid < 32 && base + tid < cnt) {
        int e = ent[tid];
        int r = e >> 1;
        if (e & 1) g_nsdf_e[r] = sdfv[tid];
        else       g_nsdf_s[r] = sdfv[tid];
    }
}

// ---------------- sampler eval: all masked rays x 100 samples, flat ----------------
__global__ __launch_bounds__(256, 3)
void samp_eval(const float* __restrict__ cam_in, const float* __restrict__ ray_in,
               const float* __restrict__ W1, const float* __restrict__ b1,
               const float* __restrict__ W2, const float* __restrict__ b2,
               const float* __restrict__ W3, const float* __restrict__ b3)
{
    const int tot = g_nmasked * 100;
    const int base = blockIdx.x * 32;
    if (base >= tot) return;

    __shared__ __align__(16) float h1s[8192];
    __shared__ float red[128];
    __shared__ float pts[96];
    __shared__ float sdfv[32];
    __shared__ int   s_r[32], s_i[32];

    const int tid = threadIdx.x;
    const float b3v = b3[0];
    if (tid < 32) {
        int idx = base + tid;
        int cidx = (idx < tot) ? idx : (tot - 1);
        int li = cidx / 100;
        int i  = cidx - li * 100;
        int r  = g_mlist[li];
        s_r[tid] = r; s_i[tid] = i;
        float smin = g_smin[r];
        float dz = g_smax[r] - smin;
        float z = fmaf(dz, (float)i * INV99, smin);
        pts[tid*3+0] = fmaf(z, ray_in[r*3+0], cam_in[r*3+0]);
        pts[tid*3+1] = fmaf(z, ray_in[r*3+1], cam_in[r*3+1]);
        pts[tid*3+2] = fmaf(z, ray_in[r*3+2], cam_in[r*3+2]);
    }
    __syncthreads();
    sdf_eval32(W1, b1, W2, b2, W3, b3v, pts, h1s, red, sdfv);
    if (tid < 32 && base + tid < tot)
        g_sdf[s_r[tid] * 100 + s_i[tid]] = sdfv[tid];
}

// ---------------- argmin + bracket ----------------
__global__ __launch_bounds__(128, 8)
void argmin_kernel(const float* __restrict__ cam_in, const float* __restrict__ ray_in,
                   float* __restrict__ out, int R)
{
    const int lane = threadIdx.x & 31;
    const int li = blockIdx.x * 4 + (threadIdx.x >> 5);
    if (li >= g_nmasked) return;
    const int r = g_mlist[li];
    const float* s100 = g_sdf + r * 100;

    float bt = 3.0e38f; int bi = 0;
    for (int i = lane; i < 100; i += 32) {
        float s = s100[i];
        float sg = (s > 0.f) ? 1.f : ((s < 0.f) ? -1.f : 0.f);
        float t = sg * (float)(100 - i);
        if (t < bt) { bt = t; bi = i; }
    }
#pragma unroll
    for (int off = 16; off; off >>= 1) {
        float t2 = __shfl_down_sync(0xffffffffu, bt, off);
        int   i2 = __shfl_down_sync(0xffffffffu, bi, off);
        if (t2 < bt || (t2 == bt && i2 < bi)) { bt = t2; bi = i2; }
    }
    if (lane == 0) {
        const float smin = g_smin[r];
        const float dz = g_smax[r] - smin;
        int ind = bi;
        int il = (ind + 99) % 100;     // torch's (ind-1) wrap
        float zlo = fmaf(dz, (float)il  * INV99, smin);
        float zhi = fmaf(dz, (float)ind * INV99, smin);
        float slo = s100[il], shi = s100[ind];
        if (shi < 0.f) {
            float den = shi - slo; if (fabsf(den) <= 1e-12f) den = 1e-12f;
            float zp = -slo * (zhi - zlo) / den + zlo;
            g_zlo[r] = zlo; g_zhi[r] = zhi; g_slo[r] = slo; g_shi[r] = shi; g_zp[r] = zp;
            int pos = atomicAdd(&g_seccount, 1);
            g_seclist[pos] = r;
        } else {
            float dist = zhi;
            float cx = cam_in[r*3+0], cy = cam_in[r*3+1], cz = cam_in[r*3+2];
            float rx = ray_in[r*3+0], ry = ray_in[r*3+1], rz = ray_in[r*3+2];
            out[r*3+0] = fmaf(dist, rx, cx);
            out[r*3+1] = fmaf(dist, ry, cy);
            out[r*3+2] = fmaf(dist, rz, cz);
            out[R*3+r] = 0.f;
            out[R*4+r] = dist;
        }
    }
}

// ---------------- batched secant: 32 rays per block ----------------
__global__ __launch_bounds__(256, 3)
void secant_kernel(const float* __restrict__ cam_in, const float* __restrict__ ray_in,
                   const float* __restrict__ W1, const float* __restrict__ b1,
                   const float* __restrict__ W2, const float* __restrict__ b2,
                   const float* __restrict__ W3, const float* __restrict__ b3,
                   float* __restrict__ out, int R)
{
    const int base = blockIdx.x * 32;
    if (base >= g_seccount) return;

    __shared__ __align__(16) float h1s[8192];
    __shared__ float red[128];
    __shared__ float pts[96];
    __shared__ float sdfv[32];
    __shared__ float s_cr[32][6];
    __shared__ float s_zlo[32], s_zhi[32], s_slo[32], s_shi[32], s_zp[32];
    __shared__ int   s_r[32];
    __shared__ int   s_n;

    const int tid = threadIdx.x;
    const float b3v = b3[0];
    if (tid == 0) {
        int c = g_seccount - base;
        s_n = (c < 32) ? c : 32;
    }
    __syncthreads();
    const int n = s_n;
    if (tid < 32) {
        int li = (tid < n) ? tid : 0;
        int r = g_seclist[base + li];
        s_r[tid] = (tid < n) ? r : -1;
        s_zlo[tid] = g_zlo[r]; s_zhi[tid] = g_zhi[r];
        s_slo[tid] = g_slo[r]; s_shi[tid] = g_shi[r];
        s_zp[tid]  = g_zp[r];
        s_cr[tid][0] = cam_in[r*3+0]; s_cr[tid][1] = cam_in[r*3+1]; s_cr[tid][2] = cam_in[r*3+2];
        s_cr[tid][3] = ray_in[r*3+0]; s_cr[tid][4] = ray_in[r*3+1]; s_cr[tid][5] = ray_in[r*3+2];
    }
    __syncthreads();

    for (int it = 0; it < 8; ++it) {
        if (tid < 32) {
            float zp = s_zp[tid];
            pts[tid*3+0] = fmaf(zp, s_cr[tid][3], s_cr[tid][0]);
            pts[tid*3+1] = fmaf(zp, s_cr[tid][4], s_cr[tid][1]);
            pts[tid*3+2] = fmaf(zp, s_cr[tid][5], s_cr[tid][2]);
        }
        __syncthreads();
        sdf_eval32(W1, b1, W2, b2, W3, b3v, pts, h1s, red, sdfv);
        if (tid < 32) {
            float mid = sdfv[tid];
            if (mid > 0.f) { s_zlo[tid] = s_zp[tid]; s_slo[tid] = mid; }
            if (mid < 0.f) { s_zhi[tid] = s_zp[tid]; s_shi[tid] = mid; }
            float den = s_shi[tid] - s_slo[tid];
            if (fabsf(den) <= 1e-12f) den = 1e-12f;
            s_zp[tid] = -s_slo[tid] * (s_zhi[tid] - s_zlo[tid]) / den + s_zlo[tid];
        }
        __syncthreads();
    }

    if (tid < n) {
        int r = s_r[tid];
        float dist = s_zp[tid];
        out[r*3+0] = fmaf(dist, s_cr[tid][3], s_cr[tid][0]);
        out[r*3+1] = fmaf(dist, s_cr[tid][4], s_cr[tid][1]);
        out[r*3+2] = fmaf(dist, s_cr[tid][5], s_cr[tid][2]);
        out[R*3+r] = 1.f;
        out[R*4+r] = dist;
    }
}

// ---------------- launch ----------------
extern "C" void kernel_launch(void* const* d_in, const int* in_sizes, int n_in,
                              void* d_out, int out_size)
{
    const float* cam  = (const float*)d_in[0];
    const float* rays = (const float*)d_in[1];
    // d_in[2] = object_mask (unused by the eval-mode forward)
    const float* W1 = (const float*)d_in[3];
    const float* b1 = (const float*)d_in[4];
    const float* W2 = (const float*)d_in[5];
    const float* b2 = (const float*)d_in[6];
    const float* W3 = (const float*)d_in[7];
    const float* b3 = (const float*)d_in[8];
    int R = in_sizes[0] / 3;
    if (R > RMAX) R = RMAX;
    float* out = (float*)d_out;

    const int nb = (R + 255) / 256;
    const int ne = (2 * R + 31) / 32;

    init_kernel<<<1, 64>>>();
    k_tr_init<<<nb, 256>>>(cam, rays, R);
    eval_trace<<<ne, 256>>>(cam, rays, W1, b1, W2, b2, W3, b3, 0);
    for (int it = 0; it < 10; ++it) {
        int pa = 1 + 2 * it, pb = 2 + 2 * it;
        k_step1<<<nb, 256>>>(R, pa);
        eval_trace<<<ne, 256>>>(cam, rays, W1, b1, W2, b2, W3, b3, pa);
        k_step2<<<nb, 256>>>(R, pb);
        eval_trace<<<ne, 256>>>(cam, rays, W1, b1, W2, b2, W3, b3, pb);
    }
    k_final<<<nb, 256>>>(cam, rays, out, R);
    samp_eval<<<(R * 100 + 31) / 32, 256>>>(cam, rays, W1, b1, W2, b2, W3, b3);
    argmin_kernel<<<(R + 3) / 4, 128>>>(cam, rays, out, R);
    secant_kernel<<<(R + 31) / 32, 256>>>(cam, rays, W1, b1, W2, b2, W3, b3, out, R);
}

// round 6
// speedup vs baseline: 1.4756x; 1.0663x over previous
#include <cuda_runtime.h>
#include <math.h>

// ---------------- constants ----------------
#define RMAX 8192
static constexpr float SDF_T = 5e-05f;
static constexpr float INV99 = 1.0f / 99.0f;

// ---------------- inter-kernel scratch ----------------
__device__ float g_acc_s[RMAX], g_acc_e[RMAX];
__device__ float g_nsdf_s[RMAX], g_nsdf_e[RMAX];
__device__ float g_csdf_s[RMAX], g_csdf_e[RMAX];
__device__ int   g_unfin_s[RMAX], g_unfin_e[RMAX];
__device__ float g_smin[RMAX], g_smax[RMAX];
__device__ int   g_mlist[RMAX];
__device__ int   g_nmasked;
__device__ int   g_seclist[RMAX];
__device__ int   g_seccount;
__device__ float g_zlo[RMAX], g_zhi[RMAX], g_slo[RMAX], g_shi[RMAX], g_zp[RMAX];
__device__ int   g_elistA[2 * RMAX];
__device__ int   g_elistB[2 * RMAX];
__device__ int   g_ecnt[32];

__global__ void init_kernel() {
    int t = threadIdx.x;
    if (t < 32) g_ecnt[t] = 0;
    if (t == 32) g_nmasked = 0;
    if (t == 33) g_seccount = 0;
}

// ---------------- f32x2 helpers ----------------
__device__ __forceinline__ unsigned long long pack2(float a, float b) {
    unsigned long long r;
    asm("mov.b64 %0, {%1, %2};" : "=l"(r) : "f"(a), "f"(b));
    return r;
}
__device__ __forceinline__ void unpack2(unsigned long long v, float& a, float& b) {
    asm("mov.b64 {%0, %1}, %2;" : "=f"(a), "=f"(b) : "l"(v));
}
__device__ __forceinline__ unsigned long long fma2(unsigned long long a,
                                                   unsigned long long b,
                                                   unsigned long long c) {
    unsigned long long d;
    asm("fma.rn.f32x2 %0, %1, %2, %3;" : "=l"(d) : "l"(a), "l"(b), "l"(c));
    return d;
}

__device__ __forceinline__ float tanh_fast(float x) {
    x = fminf(fmaxf(x, -15.f), 15.f);
    float e = __expf(2.f * x);
    return (e - 1.f) * __fdividef(1.f, e + 1.f);
}

// ---------------- batched SDF eval, P = 32 points, 256 threads ----------------
__device__ __forceinline__ void sdf_eval32(
    const float* __restrict__ W1, const float* __restrict__ b1,
    const float* __restrict__ W2, const float* __restrict__ b2,
    const float* __restrict__ W3, float b3v,
    const float* pts, float* h1s, float* red, float* sdfv)
{
    const int tid = threadIdx.x;

    // ---- layer 1 ----
#pragma unroll
    for (int it = 0; it < 32; ++it) {
        int idx = it * 256 + tid;
        int k = idx >> 5;
        int p = idx & 31;
        float x = pts[p * 3 + 0], y = pts[p * 3 + 1], z = pts[p * 3 + 2];
        float v = fmaf(W1[k], x, fmaf(W1[256 + k], y, fmaf(W1[512 + k], z, b1[k])));
        h1s[idx] = tanh_fast(v);
    }
    __syncthreads();

    // ---- layer 2: (neuron pair) x (point half) tiling ----
    const int half  = tid >> 7;
    const int npair = tid & 127;
    unsigned long long accA[8], accB[8];
#pragma unroll
    for (int q = 0; q < 8; ++q) { accA[q] = 0ull; accB[q] = 0ull; }

    const float2* W2p = reinterpret_cast<const float2*>(W2) + npair;
    const float* hbase = h1s + half * 16;

    float2 w0[2], w1[2];
#pragma unroll
    for (int u = 0; u < 2; ++u) w0[u] = W2p[u * 128];
#pragma unroll
    for (int u = 0; u < 2; ++u) w1[u] = W2p[(2 + u) * 128];

#pragma unroll 1
    for (int k0 = 0; k0 < 256; k0 += 2) {
        float2 wn[2];
        int kp = k0 + 4;
        if (kp < 256) {
#pragma unroll
            for (int u = 0; u < 2; ++u) wn[u] = W2p[(kp + u) * 128];
        } else {
#pragma unroll
            for (int u = 0; u < 2; ++u) wn[u] = make_float2(0.f, 0.f);
        }
#pragma unroll
        for (int u = 0; u < 2; ++u) {
            unsigned long long wA = pack2(w0[u].x, w0[u].x);
            unsigned long long wB = pack2(w0[u].y, w0[u].y);
            const ulonglong2* h2 =
                reinterpret_cast<const ulonglong2*>(hbase + (k0 + u) * 32);
            ulonglong2 v0 = h2[0], v1 = h2[1], v2 = h2[2], v3 = h2[3];
            accA[0] = fma2(v0.x, wA, accA[0]); accB[0] = fma2(v0.x, wB, accB[0]);
            accA[1] = fma2(v0.y, wA, accA[1]); accB[1] = fma2(v0.y, wB, accB[1]);
            accA[2] = fma2(v1.x, wA, accA[2]); accB[2] = fma2(v1.x, wB, accB[2]);
            accA[3] = fma2(v1.y, wA, accA[3]); accB[3] = fma2(v1.y, wB, accB[3]);
            accA[4] = fma2(v2.x, wA, accA[4]); accB[4] = fma2(v2.x, wB, accB[4]);
            accA[5] = fma2(v2.y, wA, accA[5]); accB[5] = fma2(v2.y, wB, accB[5]);
            accA[6] = fma2(v3.x, wA, accA[6]); accB[6] = fma2(v3.x, wB, accB[6]);
            accA[7] = fma2(v3.y, wA, accA[7]); accB[7] = fma2(v3.y, wB, accB[7]);
        }
#pragma unroll
        for (int u = 0; u < 2; ++u) { w0[u] = w1[u]; w1[u] = wn[u]; }
    }

    // ---- layer 3 ----
    float2 b2v = reinterpret_cast<const float2*>(b2)[npair];
    float2 w3v = reinterpret_cast<const float2*>(W3)[npair];
    const int sub = (tid >> 5) & 3;
#pragma unroll
    for (int q = 0; q < 8; ++q) {
        float a0, a1, c0, c1;
        unpack2(accA[q], a0, a1);
        unpack2(accB[q], c0, c1);
        float m0 = tanh_fast(a0 + b2v.x) * w3v.x + tanh_fast(c0 + b2v.y) * w3v.y;
        float m1 = tanh_fast(a1 + b2v.x) * w3v.x + tanh_fast(c1 + b2v.y) * w3v.y;
#pragma unroll
        for (int off = 16; off; off >>= 1) {
            m0 += __shfl_down_sync(0xffffffffu, m0, off);
            m1 += __shfl_down_sync(0xffffffffu, m1, off);
        }
        if ((tid & 31) == 0) {
            int p0 = half * 16 + 2 * q;
            red[p0 * 4 + sub] = m0;
            red[(p0 + 1) * 4 + sub] = m1;
        }
    }
    __syncthreads();
    if (tid < 32) {
        float s = red[tid * 4 + 0] + red[tid * 4 + 1] + red[tid * 4 + 2] + red[tid * 4 + 3];
        float x = pts[tid * 3 + 0], y = pts[tid * 3 + 1], z = pts[tid * 3 + 2];
        float base = sqrtf(fmaf(x, x, fmaf(y, y, fmaf(z, z, 1e-12f)))) - 0.6f;
        sdfv[tid] = base + 0.05f * (s + b3v);
    }
    __syncthreads();
}

// ---------------- trace step kernels ----------------
__global__ __launch_bounds__(256)
void k_tr_init(const float* __restrict__ cam_in, const float* __restrict__ ray_in, int R)
{
    int r = blockIdx.x * 256 + threadIdx.x;
    if (r >= R) return;
    float cx = cam_in[r*3+0], cy = cam_in[r*3+1], cz = cam_in[r*3+2];
    float rx = ray_in[r*3+0], ry = ray_in[r*3+1], rz = ray_in[r*3+2];
    float dt = rx*cx + ry*cy + rz*cz;
    float cc = cx*cx + cy*cy + cz*cz;
    float under = dt*dt - (cc - 1.0f);
    int mi = (under > 0.f) ? 1 : 0;
    float sq = sqrtf(mi ? under : 1.0f);
    float i0 = mi ? fmaxf(-sq - dt, 0.f) : 0.f;
    float i1 = mi ? fmaxf( sq - dt, 0.f) : 0.f;
    g_acc_s[r] = i0; g_acc_e[r] = i1;
    g_unfin_s[r] = mi; g_unfin_e[r] = mi;
    g_nsdf_s[r] = 0.f; g_nsdf_e[r] = 0.f;
    if (mi) {
        int pos = atomicAdd(&g_ecnt[0], 2);
        g_elistA[pos]     = (r << 1);
        g_elistA[pos + 1] = (r << 1) | 1;
    }
}

// csdf gating + advance; applies deferred (acc_s<acc_e) gate from previous iter
__global__ __launch_bounds__(256)
void k_step1(int R, int phase, int apply_lt)
{
    int r = blockIdx.x * 256 + threadIdx.x;
    if (r >= R) return;
    float as = g_acc_s[r], ae = g_acc_e[r];
    int lt = apply_lt ? ((as < ae) ? 1 : 0) : 1;
    int us0 = g_unfin_s[r] & lt;
    int ue0 = g_unfin_e[r] & lt;

    float cs = us0 ? g_nsdf_s[r] : 0.f;
    cs = (cs <= SDF_T) ? 0.f : cs;
    int us = us0 & ((cs > SDF_T) ? 1 : 0);
    float ce = ue0 ? g_nsdf_e[r] : 0.f;
    ce = (ce <= SDF_T) ? 0.f : ce;
    int ue = ue0 & ((ce > SDF_T) ? 1 : 0);

    g_unfin_s[r] = us; g_unfin_e[r] = ue;
    g_csdf_s[r] = cs; g_csdf_e[r] = ce;
    g_acc_s[r] = as + cs;
    g_acc_e[r] = ae - ce;

    int n = us + ue;
    if (n) {
        int pos = atomicAdd(&g_ecnt[phase], n);
        if (us) g_elistA[pos++] = (r << 1);
        if (ue) g_elistA[pos]   = (r << 1) | 1;
    }
}

__global__ __launch_bounds__(256)
void k_final(const float* __restrict__ cam_in, const float* __restrict__ ray_in,
             float* __restrict__ out, int R)
{
    int r = blockIdx.x * 256 + threadIdx.x;
    if (r >= R) return;
    float as = g_acc_s[r], ae = g_acc_e[r];
    int us = g_unfin_s[r] & ((as < ae) ? 1 : 0);   // deferred lt from last iter
    float cs = us ? g_nsdf_s[r] : 0.f;
    cs = (cs <= SDF_T) ? 0.f : cs;
    int mask = us & ((cs > SDF_T) ? 1 : 0);
    g_smin[r] = as; g_smax[r] = ae;
    if (mask) {
        int pos = atomicAdd(&g_nmasked, 1);
        g_mlist[pos] = r;
    }
    float cx = cam_in[r*3+0], cy = cam_in[r*3+1], cz = cam_in[r*3+2];
    float rx = ray_in[r*3+0], ry = ray_in[r*3+1], rz = ray_in[r*3+2];
    out[r*3+0] = fmaf(as, rx, cx);
    out[r*3+1] = fmaf(as, ry, cy);
    out[r*3+2] = fmaf(as, rz, cz);
    out[R*3+r] = (as < ae) ? 1.f : 0.f;
    out[R*4+r] = as;
}

// ---------------- plain eval over a compacted list (A or B) ----------------
__global__ __launch_bounds__(256, 3)
void eval_plain(const float* __restrict__ cam_in, const float* __restrict__ ray_in,
                const float* __restrict__ W1, const float* __restrict__ b1,
                const float* __restrict__ W2, const float* __restrict__ b2,
                const float* __restrict__ W3, const float* __restrict__ b3,
                int phase, int useB)
{
    const int cnt = g_ecnt[phase];
    const int base = blockIdx.x * 32;
    if (base >= cnt) return;
    const int* lst = useB ? g_elistB : g_elistA;

    __shared__ __align__(16) float h1s[8192];
    __shared__ float red[128];
    __shared__ float pts[96];
    __shared__ float sdfv[32];
    __shared__ int   ent[32];

    const int tid = threadIdx.x;
    const float b3v = b3[0];
    if (tid < 32) {
        int i = base + tid;
        int e = lst[(i < cnt) ? i : (cnt - 1)];
        ent[tid] = e;
        int r = e >> 1;
        float a = (e & 1) ? g_acc_e[r] : g_acc_s[r];
        pts[tid*3+0] = fmaf(a, ray_in[r*3+0], cam_in[r*3+0]);
        pts[tid*3+1] = fmaf(a, ray_in[r*3+1], cam_in[r*3+1]);
        pts[tid*3+2] = fmaf(a, ray_in[r*3+2], cam_in[r*3+2]);
    }
    __syncthreads();
    sdf_eval32(W1, b1, W2, b2, W3, b3v, pts, h1s, red, sdfv);
    if (tid < 32 && base + tid < cnt) {
        int e = ent[tid];
        int r = e >> 1;
        if (e & 1) g_nsdf_e[r] = sdfv[tid];
        else       g_nsdf_s[r] = sdfv[tid];
    }
}

// ---------------- eval + fused line-search step (reads A, emits B) ----------------
__global__ __launch_bounds__(256, 3)
void eval_fused(const float* __restrict__ cam_in, const float* __restrict__ ray_in,
                const float* __restrict__ W1, const float* __restrict__ b1,
                const float* __restrict__ W2, const float* __restrict__ b2,
                const float* __restrict__ W3, const float* __restrict__ b3,
                int phaseA, int phaseB)
{
    const int cnt = g_ecnt[phaseA];
    const int base = blockIdx.x * 32;
    if (base >= cnt) return;

    __shared__ __align__(16) float h1s[8192];
    __shared__ float red[128];
    __shared__ float pts[96];
    __shared__ float sdfv[32];
    __shared__ int   ent[32];

    const int tid = threadIdx.x;
    const float b3v = b3[0];
    if (tid < 32) {
        int i = base + tid;
        int e = g_elistA[(i < cnt) ? i : (cnt - 1)];
        ent[tid] = e;
        int r = e >> 1;
        float a = (e & 1) ? g_acc_e[r] : g_acc_s[r];
        pts[tid*3+0] = fmaf(a, ray_in[r*3+0], cam_in[r*3+0]);
        pts[tid*3+1] = fmaf(a, ray_in[r*3+1], cam_in[r*3+1]);
        pts[tid*3+2] = fmaf(a, ray_in[r*3+2], cam_in[r*3+2]);
    }
    __syncthreads();
    sdf_eval32(W1, b1, W2, b2, W3, b3v, pts, h1s, red, sdfv);
    if (tid < 32 && base + tid < cnt) {
        int e = ent[tid];
        int r = e >> 1;
        float ns = sdfv[tid];
        bool np = (ns < 0.f);
        if (e & 1) {
            g_nsdf_e[r] = ns;
            if (np) g_acc_e[r] += 0.5f * g_csdf_e[r];
        } else {
            g_nsdf_s[r] = ns;
            if (np) g_acc_s[r] -= 0.5f * g_csdf_s[r];
        }
        if (np) {
            int pos = atomicAdd(&g_ecnt[phaseB], 1);
            g_elistB[pos] = e;
        }
    }
}

// ---------------- sampler: per-masked-ray block, chunked early-exit ----------------
__global__ __launch_bounds__(256, 3)
void samp_kernel(const float* __restrict__ cam_in, const float* __restrict__ ray_in,
                 const float* __restrict__ W1, const float* __restrict__ b1,
                 const float* __restrict__ W2, const float* __restrict__ b2,
                 const float* __restrict__ W3, const float* __restrict__ b3,
                 float* __restrict__ out, int R)
{
    const int li = blockIdx.x;
    if (li >= g_nmasked) return;      // uniform early-exit before any sync
    const int r = g_mlist[li];

    __shared__ __align__(16) float h1s[8192];
    __shared__ float red[128];
    __shared__ float pts[96];
    __shared__ float sdfv[32];
    __shared__ float s_all[100];
    __shared__ float s_cr[6];
    __shared__ int   s_found;

    const int tid = threadIdx.x;
    const float b3v = b3[0];
    if (tid < 6)
        s_cr[tid] = (tid < 3) ? cam_in[r * 3 + tid] : ray_in[r * 3 + tid - 3];
    if (tid == 0) s_found = -1;
    const float smin = g_smin[r];
    const float dz = g_smax[r] - smin;
    __syncthreads();

    // chunks: 32,32,32,4 — stop at first chunk containing a negative sdf
    for (int c = 0; c < 4; ++c) {
        const int cbase = c * 32;
        const int cnt = (100 - cbase < 32) ? (100 - cbase) : 32;
        if (tid < 32) {
            int i = cbase + tid; if (i > 99) i = 99;
            float z = fmaf(dz, (float)i * INV99, smin);
            pts[tid*3+0] = fmaf(z, s_cr[3], s_cr[0]);
            pts[tid*3+1] = fmaf(z, s_cr[4], s_cr[1]);
            pts[tid*3+2] = fmaf(z, s_cr[5], s_cr[2]);
        }
        __syncthreads();
        sdf_eval32(W1, b1, W2, b2, W3, b3v, pts, h1s, red, sdfv);
        if (tid < 32) {
            if (tid < cnt) s_all[cbase + tid] = sdfv[tid];
            bool neg = (tid < cnt) && (sdfv[tid] < 0.f);
            unsigned m = __ballot_sync(0xffffffffu, neg);
            if (tid == 0 && m) s_found = cbase + (__ffs(m) - 1);
        }
        __syncthreads();
        if (s_found >= 0) break;
    }

    if (tid == 0) {
        int ind;
        if (s_found >= 0) {
            ind = s_found;                 // first negative wins argmin
        } else {
            ind = 99;                      // all evaluated; first zero else 99
            for (int i = 0; i < 100; ++i)
                if (s_all[i] == 0.f) { ind = i; break; }
        }
        int il = (ind >= 1) ? (ind - 1) : 99;   // ind==0 impossible (sdf[0]>thr)
        if (il > ind) il = 0;                   // defensive (unreachable)
        float zlo = fmaf(dz, (float)il  * INV99, smin);
        float zhi = fmaf(dz, (float)ind * INV99, smin);
        float slo = s_all[il], shi = s_all[ind];
        if (shi < 0.f) {
            float den = shi - slo; if (fabsf(den) <= 1e-12f) den = 1e-12f;
            float zp = -slo * (zhi - zlo) / den + zlo;
            g_zlo[r] = zlo; g_zhi[r] = zhi; g_slo[r] = slo; g_shi[r] = shi; g_zp[r] = zp;
            int pos = atomicAdd(&g_seccount, 1);
            g_seclist[pos] = r;
        } else {
            float dist = zhi;
            out[r*3+0] = fmaf(dist, s_cr[3], s_cr[0]);
            out[r*3+1] = fmaf(dist, s_cr[4], s_cr[1]);
            out[r*3+2] = fmaf(dist, s_cr[5], s_cr[2]);
            out[R*3+r] = 0.f;
            out[R*4+r] = dist;
        }
    }
}

// ---------------- batched secant: 32 rays per block ----------------
__global__ __launch_bounds__(256, 3)
void secant_kernel(const float* __restrict__ cam_in, const float* __restrict__ ray_in,
                   const float* __restrict__ W1, const float* __restrict__ b1,
                   const float* __restrict__ W2, const float* __restrict__ b2,
                   const float* __restrict__ W3, const float* __restrict__ b3,
                   float* __restrict__ out, int R)
{
    const int base = blockIdx.x * 32;
    if (base >= g_seccount) return;

    __shared__ __align__(16) float h1s[8192];
    __shared__ float red[128];
    __shared__ float pts[96];
    __shared__ float sdfv[32];
    __shared__ float s_cr[32][6];
    __shared__ float s_zlo[32], s_zhi[32], s_slo[32], s_shi[32], s_zp[32];
    __shared__ int   s_r[32];
    __shared__ int   s_n;

    const int tid = threadIdx.x;
    const float b3v = b3[0];
    if (tid == 0) {
        int c = g_seccount - base;
        s_n = (c < 32) ? c : 32;
    }
    __syncthreads();
    const int n = s_n;
    if (tid < 32) {
        int li = (tid < n) ? tid : 0;
        int r = g_seclist[base + li];
        s_r[tid] = (tid < n) ? r : -1;
        s_zlo[tid] = g_zlo[r]; s_zhi[tid] = g_zhi[r];
        s_slo[tid] = g_slo[r]; s_shi[tid] = g_shi[r];
        s_zp[tid]  = g_zp[r];
        s_cr[tid][0] = cam_in[r*3+0]; s_cr[tid][1] = cam_in[r*3+1]; s_cr[tid][2] = cam_in[r*3+2];
        s_cr[tid][3] = ray_in[r*3+0]; s_cr[tid][4] = ray_in[r*3+1]; s_cr[tid][5] = ray_in[r*3+2];
    }
    __syncthreads();

    for (int it = 0; it < 8; ++it) {
        if (tid < 32) {
            float zp = s_zp[tid];
            pts[tid*3+0] = fmaf(zp, s_cr[tid][3], s_cr[tid][0]);
            pts[tid*3+1] = fmaf(zp, s_cr[tid][4], s_cr[tid][1]);
            pts[tid*3+2] = fmaf(zp, s_cr[tid][5], s_cr[tid][2]);
        }
        __syncthreads();
        sdf_eval32(W1, b1, W2, b2, W3, b3v, pts, h1s, red, sdfv);
        if (tid < 32) {
            float mid = sdfv[tid];
            if (mid > 0.f) { s_zlo[tid] = s_zp[tid]; s_slo[tid] = mid; }
            if (mid < 0.f) { s_zhi[tid] = s_zp[tid]; s_shi[tid] = mid; }
            float den = s_shi[tid] - s_slo[tid];
            if (fabsf(den) <= 1e-12f) den = 1e-12f;
            s_zp[tid] = -s_slo[tid] * (s_zhi[tid] - s_zlo[tid]) / den + s_zlo[tid];
        }
        __syncthreads();
    }

    if (tid < n) {
        int r = s_r[tid];
        float dist = s_zp[tid];
        out[r*3+0] = fmaf(dist, s_cr[tid][3], s_cr[tid][0]);
        out[r*3+1] = fmaf(dist, s_cr[tid][4], s_cr[tid][1]);
        out[r*3+2] = fmaf(dist, s_cr[tid][5], s_cr[tid][2]);
        out[R*3+r] = 1.f;
        out[R*4+r] = dist;
    }
}

// ---------------- launch ----------------
extern "C" void kernel_launch(void* const* d_in, const int* in_sizes, int n_in,
                              void* d_out, int out_size)
{
    const float* cam  = (const float*)d_in[0];
    const float* rays = (const float*)d_in[1];
    // d_in[2] = object_mask (unused by the eval-mode forward)
    const float* W1 = (const float*)d_in[3];
    const float* b1 = (const float*)d_in[4];
    const float* W2 = (const float*)d_in[5];
    const float* b2 = (const float*)d_in[6];
    const float* W3 = (const float*)d_in[7];
    const float* b3 = (const float*)d_in[8];
    int R = in_sizes[0] / 3;
    if (R > RMAX) R = RMAX;
    float* out = (float*)d_out;

    const int nb = (R + 255) / 256;
    const int ne = (2 * R + 31) / 32;

    init_kernel<<<1, 64>>>();
    k_tr_init<<<nb, 256>>>(cam, rays, R);
    eval_plain<<<ne, 256>>>(cam, rays, W1, b1, W2, b2, W3, b3, 0, 0);
    for (int it = 0; it < 10; ++it) {
        int pa = 1 + 2 * it, pb = 2 + 2 * it;
        k_step1<<<nb, 256>>>(R, pa, (it > 0) ? 1 : 0);
        eval_fused<<<ne, 256>>>(cam, rays, W1, b1, W2, b2, W3, b3, pa, pb);
        eval_plain<<<ne, 256>>>(cam, rays, W1, b1, W2, b2, W3, b3, pb, 1);
    }
    k_final<<<nb, 256>>>(cam, rays, out, R);
    samp_kernel<<<R, 256>>>(cam, rays, W1, b1, W2, b2, W3, b3, out, R);
    secant_kernel<<<(R + 31) / 32, 256>>>(cam, rays, W1, b1, W2, b2, W3, b3, out, R);
}